// round 1
// baseline (speedup 1.0000x reference)
#include <cuda_runtime.h>
#include <math.h>

// Scratch for Q/K/V projections: [B*S, D_Q] = [8192, 512] each
static __device__ float g_Q[8192ul * 512];
static __device__ float g_K[8192ul * 512];
static __device__ float g_V[8192ul * 512];

#define TILE 64
#define KT 16

// C[z][m,n] = alpha * sum_k A[z][m,k] * Bop(k,n) (+ bias[n])
//   NT: Bop(k,n) = B[z][n*ldb + k]   (B row-major [N,K])
//   NN: Bop(k,n) = B[z][k*ldb + n]   (B row-major [K,N])
// All dims must be multiples of 64 (M,N) and 16 (K). They are.
template <bool NT>
__global__ __launch_bounds__(256) void gemm_kernel(
    const float* __restrict__ A, const float* __restrict__ B,
    const float* __restrict__ bias, float* __restrict__ C,
    int K, int lda, int ldb, int ldc,
    long sA, long sB, long sC, float alpha)
{
    __shared__ float As[KT][TILE];
    __shared__ float Bs[KT][TILE];

    const float* Ab = A + (long)blockIdx.z * sA;
    const float* Bb = B + (long)blockIdx.z * sB;
    float* Cb = C + (long)blockIdx.z * sC;

    const int m0 = blockIdx.y * TILE;
    const int n0 = blockIdx.x * TILE;
    const int tid = threadIdx.x;
    const int tx = tid & 15;   // output column group
    const int ty = tid >> 4;   // output row group

    float acc[4][4] = {};

    for (int k0 = 0; k0 < K; k0 += KT) {
        // A tile: 64 rows x 16 k, stored transposed As[k][m]; float4 along k
        {
            int m  = tid >> 2;
            int kk = (tid & 3) << 2;
            float4 v = *reinterpret_cast<const float4*>(Ab + (long)(m0 + m) * lda + k0 + kk);
            As[kk + 0][m] = v.x; As[kk + 1][m] = v.y;
            As[kk + 2][m] = v.z; As[kk + 3][m] = v.w;
        }
        if (NT) {
            int n  = tid >> 2;
            int kk = (tid & 3) << 2;
            float4 v = *reinterpret_cast<const float4*>(Bb + (long)(n0 + n) * ldb + k0 + kk);
            Bs[kk + 0][n] = v.x; Bs[kk + 1][n] = v.y;
            Bs[kk + 2][n] = v.z; Bs[kk + 3][n] = v.w;
        } else {
            int kk = tid >> 4;
            int n  = (tid & 15) << 2;
            float4 v = *reinterpret_cast<const float4*>(Bb + (long)(k0 + kk) * ldb + n0 + n);
            *reinterpret_cast<float4*>(&Bs[kk][n]) = v;
        }
        __syncthreads();

        #pragma unroll
        for (int kk = 0; kk < KT; kk++) {
            float4 a = *reinterpret_cast<const float4*>(&As[kk][ty << 2]);
            float4 b = *reinterpret_cast<const float4*>(&Bs[kk][tx << 2]);
            acc[0][0] += a.x * b.x; acc[0][1] += a.x * b.y; acc[0][2] += a.x * b.z; acc[0][3] += a.x * b.w;
            acc[1][0] += a.y * b.x; acc[1][1] += a.y * b.y; acc[1][2] += a.y * b.z; acc[1][3] += a.y * b.w;
            acc[2][0] += a.z * b.x; acc[2][1] += a.z * b.y; acc[2][2] += a.z * b.z; acc[2][3] += a.z * b.w;
            acc[3][0] += a.w * b.x; acc[3][1] += a.w * b.y; acc[3][2] += a.w * b.z; acc[3][3] += a.w * b.w;
        }
        __syncthreads();
    }

    float bv0 = 0.f, bv1 = 0.f, bv2 = 0.f, bv3 = 0.f;
    if (bias) {
        float4 bb = *reinterpret_cast<const float4*>(bias + n0 + (tx << 2));
        bv0 = bb.x; bv1 = bb.y; bv2 = bb.z; bv3 = bb.w;
    }
    #pragma unroll
    for (int i = 0; i < 4; i++) {
        float4 o;
        o.x = acc[i][0] * alpha + bv0;
        o.y = acc[i][1] * alpha + bv1;
        o.z = acc[i][2] * alpha + bv2;
        o.w = acc[i][3] * alpha + bv3;
        *reinterpret_cast<float4*>(Cb + (long)(m0 + (ty << 2) + i) * ldc + n0 + (tx << 2)) = o;
    }
}

// In-place row softmax: one block (256 threads) per row of length 2048
__global__ __launch_bounds__(256) void softmax_kernel(float* __restrict__ att)
{
    const int S = 2048;
    const int NPT = S / 256;  // 8 elements per thread
    float* row = att + (long)blockIdx.x * S;
    const int t = threadIdx.x;
    const int lane = t & 31;
    const int warp = t >> 5;

    __shared__ float red_max[8];
    __shared__ float red_sum[8];

    float v[NPT];
    float vmax = -1e30f;
    #pragma unroll
    for (int i = 0; i < NPT; i++) {
        v[i] = row[t + i * 256];
        vmax = fmaxf(vmax, v[i]);
    }
    #pragma unroll
    for (int o = 16; o > 0; o >>= 1)
        vmax = fmaxf(vmax, __shfl_xor_sync(0xffffffffu, vmax, o));
    if (lane == 0) red_max[warp] = vmax;
    __syncthreads();
    vmax = red_max[0];
    #pragma unroll
    for (int i = 1; i < 8; i++) vmax = fmaxf(vmax, red_max[i]);

    float sum = 0.f;
    #pragma unroll
    for (int i = 0; i < NPT; i++) {
        v[i] = __expf(v[i] - vmax);
        sum += v[i];
    }
    #pragma unroll
    for (int o = 16; o > 0; o >>= 1)
        sum += __shfl_xor_sync(0xffffffffu, sum, o);
    if (lane == 0) red_sum[warp] = sum;
    __syncthreads();
    float tot = red_sum[0];
    #pragma unroll
    for (int i = 1; i < 8; i++) tot += red_sum[i];
    float inv = 1.0f / tot;

    #pragma unroll
    for (int i = 0; i < NPT; i++)
        row[t + i * 256] = v[i] * inv;
}

extern "C" void kernel_launch(void* const* d_in, const int* in_sizes, int n_in,
                              void* d_out, int out_size)
{
    const float* x  = (const float*)d_in[0];   // [4,2048,512]
    const float* Wq = (const float*)d_in[1];   // [512,512]
    const float* bq = (const float*)d_in[2];   // [512]
    const float* Wk = (const float*)d_in[3];
    const float* bk = (const float*)d_in[4];
    const float* Wv = (const float*)d_in[5];
    const float* bv = (const float*)d_in[6];

    float* att = (float*)d_out;                         // [4,2048,2048]
    float* wtd = att + (size_t)4 * 2048 * 2048;         // [4,2048,512]

    float *Qp, *Kp, *Vp;
    cudaGetSymbolAddress((void**)&Qp, g_Q);
    cudaGetSymbolAddress((void**)&Kp, g_K);
    cudaGetSymbolAddress((void**)&Vp, g_V);

    const int B = 4, S = 2048, D = 512;
    const long QKV_STRIDE = (long)S * D;        // per-batch Q/K/V stride
    const long ATT_STRIDE = (long)S * S;

    dim3 blk(256);

    // QKV projections: [8192,512] = x[8192,512] @ W^T + b   (NT)
    dim3 gproj(D / TILE, (B * S) / TILE, 1);
    gemm_kernel<true><<<gproj, blk>>>(x, Wq, bq, Qp, D, D, D, D, 0, 0, 0, 1.0f);
    gemm_kernel<true><<<gproj, blk>>>(x, Wk, bk, Kp, D, D, D, D, 0, 0, 0, 1.0f);
    gemm_kernel<true><<<gproj, blk>>>(x, Wv, bv, Vp, D, D, D, D, 0, 0, 0, 1.0f);

    // scores: att[b] = (Q[b] @ K[b]^T) * 1/sqrt(512)   (NT, batched)
    float scale = 1.0f / sqrtf((float)D);
    dim3 gscore(S / TILE, S / TILE, B);
    gemm_kernel<true><<<gscore, blk>>>(Qp, Kp, nullptr, att,
                                       D, D, D, S,
                                       QKV_STRIDE, QKV_STRIDE, ATT_STRIDE, scale);

    // softmax in place over last dim
    softmax_kernel<<<B * S, blk>>>(att);

    // weighted: wtd[b] = att[b] @ V[b]   (NN, batched)
    dim3 gwtd(D / TILE, S / TILE, B);
    gemm_kernel<false><<<gwtd, blk>>>(att, Vp, nullptr, wtd,
                                      S, S, D, D,
                                      ATT_STRIDE, QKV_STRIDE, QKV_STRIDE, 1.0f);
}

// round 3
// speedup vs baseline: 2.8658x; 2.8658x over previous
#include <cuda_runtime.h>
#include <cuda_bf16.h>
#include <math.h>
#include <stdint.h>

// ======================= scratch (static, allocation-free) =======================
static __device__ __nv_bfloat16 g_Xh[8192UL * 512], g_Xl[8192UL * 512];
static __device__ __nv_bfloat16 g_Wh[3UL * 512 * 512], g_Wl[3UL * 512 * 512];
static __device__ __nv_bfloat16 g_Qh[8192UL * 512], g_Ql[8192UL * 512];
static __device__ __nv_bfloat16 g_Kh[8192UL * 512], g_Kl[8192UL * 512];
static __device__ __nv_bfloat16 g_Vth[512UL * 8192], g_Vtl[512UL * 8192];
static __device__ __nv_bfloat16 g_Ph[4UL * 2048 * 2048], g_Pl[4UL * 2048 * 2048];

// ======================= helpers (base ISA only: sm_80/sm_75 features) =======================
__device__ __forceinline__ uint32_t smem_u32(const void* p) {
    uint32_t a;
    asm("{ .reg .u64 t; cvta.to.shared.u64 t, %1; cvt.u32.u64 %0, t; }" : "=r"(a) : "l"(p));
    return a;
}
__device__ __forceinline__ void ldsm_x4(uint32_t r[4], uint32_t addr) {
    asm volatile("ldmatrix.sync.aligned.m8n8.x4.shared.b16 {%0,%1,%2,%3}, [%4];"
                 : "=r"(r[0]), "=r"(r[1]), "=r"(r[2]), "=r"(r[3]) : "r"(addr));
}
__device__ __forceinline__ void hmma(float* c, const uint32_t* a, const uint32_t* b) {
    asm volatile(
        "mma.sync.aligned.m16n8k16.row.col.f32.bf16.bf16.f32 "
        "{%0,%1,%2,%3}, {%4,%5,%6,%7}, {%8,%9}, {%0,%1,%2,%3};"
        : "+f"(c[0]), "+f"(c[1]), "+f"(c[2]), "+f"(c[3])
        : "r"(a[0]), "r"(a[1]), "r"(a[2]), "r"(a[3]), "r"(b[0]), "r"(b[1]));
}
__device__ __forceinline__ void cp16(uint32_t s, const void* g) {
    asm volatile("cp.async.cg.shared.global [%0], [%1], 16;" :: "r"(s), "l"(g) : "memory");
}

// ======================= HMMA GEMM =======================
// D[m,n] = alpha * sum_k A[m,k]*B[n,k] (+ bias[n]), hi/lo bf16 split (3 MMAs)
// EPI 0: bf16 hi/lo out at [(m0+r)*ldc + n0+c]  (+bias)   [Q/K proj]
// EPI 1: bf16 hi/lo out at [(n0+r)*ldc + m0+c]  (+bias)   [V proj, transposed]
// EPI 2: f32 out at [(m0+r)*ldc + n0+c]          (*alpha)  [scores / weighted]
#define BM 128
#define BN 128
#define BK 32
#define TILE_BYTES  (128 * 64)       // one 128x32 bf16 tile, 64B rows
#define STAGE_BYTES (4 * TILE_BYTES) // Ah, Al, Bh, Bl
#define SMEM_BYTES  (128 * 129 * 4 + 256)  // staging dominates (66048) > 2*STAGE (65536)

template <int EPI>
__global__ void __launch_bounds__(256, 1)
hmma_gemm(const __nv_bfloat16* __restrict__ Ah, const __nv_bfloat16* __restrict__ Al,
          const __nv_bfloat16* __restrict__ Bh, const __nv_bfloat16* __restrict__ Bl,
          const float* __restrict__ bias, float* __restrict__ Cf,
          __nv_bfloat16* __restrict__ Ch, __nv_bfloat16* __restrict__ Cl,
          int K, int lda, int ldb, int ldc,
          long sA, long sB, long sC, float alpha)
{
    extern __shared__ char smem_raw[];
    const uint32_t raw32 = smem_u32(smem_raw);
    const uint32_t sbase = (raw32 + 127) & ~127u;
    char* smem_al = smem_raw + (sbase - raw32);

    const int tid = threadIdx.x;
    const int w = tid >> 5, l = tid & 31;
    const int m0 = blockIdx.y * BM;
    const int n0 = blockIdx.x * BN;
    const int z = blockIdx.z;

    const __nv_bfloat16* srcs[4] = {Ah + z * sA, Al + z * sA, Bh + z * sB, Bl + z * sB};
    const int rbs[4] = {m0, m0, n0, n0};
    const int lds_[4] = {lda, lda, ldb, ldb};

    const int NC = K / BK;

    auto load_stage = [&](int c) {
        const uint32_t stg = sbase + (c & 1) * STAGE_BYTES;
        #pragma unroll
        for (int i = 0; i < 8; i++) {
            int id = tid + i * 256;
            int t = id >> 9, rem = id & 511, row = rem >> 2, ch = rem & 3;
            const __nv_bfloat16* g = srcs[t] + (long)(rbs[t] + row) * lds_[t] + (long)c * BK + ch * 8;
            uint32_t sa = stg + t * TILE_BYTES + row * 64 + ((ch ^ ((row >> 1) & 3)) << 4);
            cp16(sa, g);
        }
        asm volatile("cp.async.commit_group;" ::: "memory");
    };

    float acc[4][4][4] = {};
    const int wm = (w & 1) * 64;   // warp m-offset
    const int wn = (w >> 1) * 32;  // warp n-offset
    const int matI = l >> 3, rim = l & 7;

    load_stage(0);
    load_stage(1);

    for (int c = 0; c < NC; c++) {
        asm volatile("cp.async.wait_group 1;" ::: "memory");
        __syncthreads();
        const uint32_t stg = sbase + (c & 1) * STAGE_BYTES;

        #pragma unroll
        for (int kk = 0; kk < 2; kk++) {   // two k16 halves of the 32-wide chunk
            uint32_t fAh[4][4], fAl[4][4];
            #pragma unroll
            for (int mi = 0; mi < 4; mi++) {
                int row = wm + mi * 16 + rim + (matI & 1) * 8;
                int ch = kk * 2 + (matI >> 1);
                uint32_t off = row * 64 + ((ch ^ ((row >> 1) & 3)) << 4);
                ldsm_x4(fAh[mi], stg + off);
                ldsm_x4(fAl[mi], stg + TILE_BYTES + off);
            }
            uint32_t fB[2][2][4];   // [hi/lo][n16-pair][regs]
            #pragma unroll
            for (int p = 0; p < 2; p++) {
                int n = wn + p * 16 + (matI >> 1) * 8 + rim;
                int ch = kk * 2 + (matI & 1);
                uint32_t off = n * 64 + ((ch ^ ((n >> 1) & 3)) << 4);
                ldsm_x4(fB[0][p], stg + 2 * TILE_BYTES + off);
                ldsm_x4(fB[1][p], stg + 3 * TILE_BYTES + off);
            }
            #pragma unroll
            for (int mi = 0; mi < 4; mi++)
                #pragma unroll
                for (int ni = 0; ni < 4; ni++) {
                    const uint32_t* bh = &fB[0][ni >> 1][(ni & 1) * 2];
                    const uint32_t* bl = &fB[1][ni >> 1][(ni & 1) * 2];
                    hmma(acc[mi][ni], fAh[mi], bh);
                    hmma(acc[mi][ni], fAh[mi], bl);
                    hmma(acc[mi][ni], fAl[mi], bh);
                }
        }
        __syncthreads();
        if (c + 2 < NC) load_stage(c + 2);
        else asm volatile("cp.async.commit_group;" ::: "memory");
    }
    asm volatile("cp.async.wait_group 0;" ::: "memory");
    __syncthreads();

    // ---------------- epilogue: regs -> SMEM stage -> coalesced GMEM ----------------
    float* sf = reinterpret_cast<float*>(smem_al);   // [128][129]
    const int r_ = l >> 2, cq = (l & 3) * 2;

    #pragma unroll
    for (int mi = 0; mi < 4; mi++)
        #pragma unroll
        for (int ni = 0; ni < 4; ni++) {
            int m = wm + mi * 16 + r_;
            int n = wn + ni * 8 + cq;
            float b0 = 0.f, b1 = 0.f;
            if (EPI != 2) { b0 = bias[n0 + n]; b1 = bias[n0 + n + 1]; }
            float v00 = acc[mi][ni][0] * alpha + b0;
            float v01 = acc[mi][ni][1] * alpha + b1;
            float v10 = acc[mi][ni][2] * alpha + b0;
            float v11 = acc[mi][ni][3] * alpha + b1;
            if (EPI == 1) {
                sf[n * 129 + m] = v00;       sf[(n + 1) * 129 + m] = v01;
                sf[n * 129 + m + 8] = v10;   sf[(n + 1) * 129 + m + 8] = v11;
            } else {
                sf[m * 129 + n] = v00;       sf[m * 129 + n + 1] = v01;
                sf[(m + 8) * 129 + n] = v10; sf[(m + 8) * 129 + n + 1] = v11;
            }
        }
    __syncthreads();

    if (EPI == 2) {
        float* Cb = Cf + z * sC;
        #pragma unroll
        for (int i = 0; i < 16; i++) {
            int idx = (tid + i * 256) << 2;
            int row = idx >> 7, col = idx & 127;
            const float* p = &sf[row * 129 + col];
            float4 v = make_float4(p[0], p[1], p[2], p[3]);
            *reinterpret_cast<float4*>(Cb + (long)(m0 + row) * ldc + n0 + col) = v;
        }
    } else {
        #pragma unroll
        for (int i = 0; i < 16; i++) {
            int idx = (tid + i * 256) << 2;
            int row = idx >> 7, col = idx & 127;
            const float* p = &sf[row * 129 + col];
            uint32_t hp[2], lp[2];
            #pragma unroll
            for (int q = 0; q < 2; q++) {
                float v0 = p[2 * q], v1 = p[2 * q + 1];
                __nv_bfloat16 h0 = __float2bfloat16(v0), h1 = __float2bfloat16(v1);
                __nv_bfloat16 l0 = __float2bfloat16(v0 - __bfloat162float(h0));
                __nv_bfloat16 l1 = __float2bfloat16(v1 - __bfloat162float(h1));
                __nv_bfloat162 H = __nv_bfloat162(h0, h1), L = __nv_bfloat162(l0, l1);
                hp[q] = *reinterpret_cast<uint32_t*>(&H);
                lp[q] = *reinterpret_cast<uint32_t*>(&L);
            }
            long dst = (EPI == 0) ? ((long)(m0 + row) * ldc + n0 + col)
                                  : ((long)(n0 + row) * ldc + m0 + col);
            *reinterpret_cast<uint2*>(Ch + dst) = make_uint2(hp[0], hp[1]);
            *reinterpret_cast<uint2*>(Cl + dst) = make_uint2(lp[0], lp[1]);
        }
    }
}

// ======================= fp32 -> bf16 hi/lo conversion =======================
__global__ void cvt_kernel(const float* __restrict__ in, __nv_bfloat16* __restrict__ h,
                           __nv_bfloat16* __restrict__ l, int n)
{
    int i = blockIdx.x * blockDim.x + threadIdx.x;
    if (i < n) {
        float v = in[i];
        __nv_bfloat16 a = __float2bfloat16(v);
        h[i] = a;
        l[i] = __float2bfloat16(v - __bfloat162float(a));
    }
}

// ======================= softmax (f32 in place + bf16 hi/lo out) =======================
__global__ void __launch_bounds__(256) softmax_kernel(
    float* __restrict__ att, __nv_bfloat16* __restrict__ Ph, __nv_bfloat16* __restrict__ Pl)
{
    const int S = 2048, NPT = 8;
    const long rowoff = (long)blockIdx.x * S;
    float* row = att + rowoff;
    const int t = threadIdx.x, lane = t & 31, warp = t >> 5;

    __shared__ float red_max[8], red_sum[8];

    float v[NPT];
    float vmax = -1e30f;
    #pragma unroll
    for (int i = 0; i < NPT; i++) { v[i] = row[t + i * 256]; vmax = fmaxf(vmax, v[i]); }
    #pragma unroll
    for (int o = 16; o > 0; o >>= 1) vmax = fmaxf(vmax, __shfl_xor_sync(~0u, vmax, o));
    if (lane == 0) red_max[warp] = vmax;
    __syncthreads();
    vmax = red_max[0];
    #pragma unroll
    for (int i = 1; i < 8; i++) vmax = fmaxf(vmax, red_max[i]);

    float sum = 0.f;
    #pragma unroll
    for (int i = 0; i < NPT; i++) { v[i] = __expf(v[i] - vmax); sum += v[i]; }
    #pragma unroll
    for (int o = 16; o > 0; o >>= 1) sum += __shfl_xor_sync(~0u, sum, o);
    if (lane == 0) red_sum[warp] = sum;
    __syncthreads();
    float tot = red_sum[0];
    #pragma unroll
    for (int i = 1; i < 8; i++) tot += red_sum[i];
    float inv = 1.0f / tot;

    #pragma unroll
    for (int i = 0; i < NPT; i++) {
        float p = v[i] * inv;
        long off = rowoff + t + i * 256;
        row[t + i * 256] = p;
        __nv_bfloat16 h = __float2bfloat16(p);
        Ph[off] = h;
        Pl[off] = __float2bfloat16(p - __bfloat162float(h));
    }
}

// ======================= launch =======================
extern "C" void kernel_launch(void* const* d_in, const int* in_sizes, int n_in,
                              void* d_out, int out_size)
{
    const float* x  = (const float*)d_in[0];
    const float* Wq = (const float*)d_in[1];
    const float* bq = (const float*)d_in[2];
    const float* Wk = (const float*)d_in[3];
    const float* bk = (const float*)d_in[4];
    const float* Wv = (const float*)d_in[5];
    const float* bv = (const float*)d_in[6];

    const int B = 4, S = 2048, D = 512;
    float* att = (float*)d_out;
    float* wtd = att + (size_t)B * S * S;

    __nv_bfloat16 *Xh, *Xl, *Wh, *Wl, *Qh, *Ql, *Kh, *Kl, *Vth, *Vtl, *Ph, *Pl;
    cudaGetSymbolAddress((void**)&Xh, g_Xh);   cudaGetSymbolAddress((void**)&Xl, g_Xl);
    cudaGetSymbolAddress((void**)&Wh, g_Wh);   cudaGetSymbolAddress((void**)&Wl, g_Wl);
    cudaGetSymbolAddress((void**)&Qh, g_Qh);   cudaGetSymbolAddress((void**)&Ql, g_Ql);
    cudaGetSymbolAddress((void**)&Kh, g_Kh);   cudaGetSymbolAddress((void**)&Kl, g_Kl);
    cudaGetSymbolAddress((void**)&Vth, g_Vth); cudaGetSymbolAddress((void**)&Vtl, g_Vtl);
    cudaGetSymbolAddress((void**)&Ph, g_Ph);   cudaGetSymbolAddress((void**)&Pl, g_Pl);

    cudaFuncSetAttribute(hmma_gemm<0>, cudaFuncAttributeMaxDynamicSharedMemorySize, SMEM_BYTES);
    cudaFuncSetAttribute(hmma_gemm<1>, cudaFuncAttributeMaxDynamicSharedMemorySize, SMEM_BYTES);
    cudaFuncSetAttribute(hmma_gemm<2>, cudaFuncAttributeMaxDynamicSharedMemorySize, SMEM_BYTES);

    const int NX = B * S * D;          // 4.19M
    const int NW = D * D;              // 262144
    cvt_kernel<<<(NX + 511) / 512, 512>>>(x, Xh, Xl, NX);
    cvt_kernel<<<(NW + 511) / 512, 512>>>(Wq, Wh, Wl, NW);
    cvt_kernel<<<(NW + 511) / 512, 512>>>(Wk, Wh + NW, Wl + NW, NW);
    cvt_kernel<<<(NW + 511) / 512, 512>>>(Wv, Wh + 2 * NW, Wl + 2 * NW, NW);

    dim3 blk(256);

    // Q/K projections: [8192,512] x [512,512]^T
    dim3 gproj(D / BN, (B * S) / BM, 1);
    hmma_gemm<0><<<gproj, blk, SMEM_BYTES>>>(Xh, Xl, Wh, Wl, bq, nullptr, Qh, Ql,
                                             D, D, D, D, 0, 0, 0, 1.0f);
    hmma_gemm<0><<<gproj, blk, SMEM_BYTES>>>(Xh, Xl, Wh + NW, Wl + NW, bk, nullptr, Kh, Kl,
                                             D, D, D, D, 0, 0, 0, 1.0f);
    // V projection, transposed output Vt[512][8192]
    hmma_gemm<1><<<gproj, blk, SMEM_BYTES>>>(Xh, Xl, Wh + 2 * NW, Wl + 2 * NW, bv, nullptr, Vth, Vtl,
                                             D, D, D, 8192, 0, 0, 0, 1.0f);

    // scores: att[b] = Q[b] @ K[b]^T * scale
    const float scale = 1.0f / sqrtf((float)D);
    dim3 gsc(S / BN, S / BM, B);
    hmma_gemm<2><<<gsc, blk, SMEM_BYTES>>>(Qh, Ql, Kh, Kl, nullptr, att, nullptr, nullptr,
                                           D, D, D, S, (long)S * D, (long)S * D, (long)S * S, scale);

    // softmax (f32 in place into d_out, bf16 hi/lo for next GEMM)
    softmax_kernel<<<B * S, 256>>>(att, Ph, Pl);

    // weighted: wtd[b] = P[b] @ V[b]  (Vt is [512, 8192], per-batch column offset b*2048)
    dim3 gw(D / BN, S / BM, B);
    hmma_gemm<2><<<gw, blk, SMEM_BYTES>>>(Ph, Pl, Vth, Vtl, nullptr, wtd, nullptr, nullptr,
                                          S, S, 8192, D, (long)S * S, (long)S, (long)S * D, 1.0f);
}

// round 4
// speedup vs baseline: 3.4446x; 1.2020x over previous
#include <cuda_runtime.h>
#include <cuda_fp16.h>
#include <math.h>
#include <stdint.h>

// ======================= scratch (static, allocation-free) =======================
static __device__ __half g_Xh[8192UL * 512], g_Xl[8192UL * 512];
static __device__ __half g_Wh[3UL * 512 * 512], g_Wl[3UL * 512 * 512];
static __device__ __half g_Qh[8192UL * 512], g_Ql[8192UL * 512];
static __device__ __half g_Kh[8192UL * 512];
static __device__ __half g_Vth[512UL * 8192];
static __device__ __half g_Ph[4UL * 2048 * 2048], g_Pl[4UL * 2048 * 2048];

// ======================= helpers (base ISA: sm_80/75 features only) =======================
__device__ __forceinline__ uint32_t smem_u32(const void* p) {
    uint32_t a;
    asm("{ .reg .u64 t; cvta.to.shared.u64 t, %1; cvt.u32.u64 %0, t; }" : "=r"(a) : "l"(p));
    return a;
}
__device__ __forceinline__ void ldsm_x4(uint32_t r[4], uint32_t addr) {
    asm volatile("ldmatrix.sync.aligned.m8n8.x4.shared.b16 {%0,%1,%2,%3}, [%4];"
                 : "=r"(r[0]), "=r"(r[1]), "=r"(r[2]), "=r"(r[3]) : "r"(addr));
}
__device__ __forceinline__ void hmma(float* c, const uint32_t* a, const uint32_t* b) {
    asm volatile(
        "mma.sync.aligned.m16n8k16.row.col.f32.f16.f16.f32 "
        "{%0,%1,%2,%3}, {%4,%5,%6,%7}, {%8,%9}, {%0,%1,%2,%3};"
        : "+f"(c[0]), "+f"(c[1]), "+f"(c[2]), "+f"(c[3])
        : "r"(a[0]), "r"(a[1]), "r"(a[2]), "r"(a[3]), "r"(b[0]), "r"(b[1]));
}
__device__ __forceinline__ void cp16(uint32_t s, const void* g) {
    asm volatile("cp.async.cg.shared.global [%0], [%1], 16;" :: "r"(s), "l"(g) : "memory");
}

// ======================= HMMA GEMM (fp16 split) =======================
// D[m,n] = alpha * sum_k A[m,k]*B[n,k] (+ bias[n])
//   A split hi/lo always; B lo used only when BLO (3-term: AhBh+AhBl+AlBh, else AhBh+AlBh)
// EPI 0: fp16 out at [(m0+r)*ldc + n0+c]  (+bias), lo written iff WLO   [Q/K proj]
// EPI 1: fp16 out at [(n0+r)*ldc + m0+c]  (+bias), transposed           [V proj]
// EPI 2: f32 out at [(m0+r)*ldc + n0+c]   (*alpha)                      [scores / weighted]
#define BM 128
#define BN 128
#define BK 32
#define TILE_BYTES  (128 * 64)        // one 128x32 fp16 tile, 64B rows
#define SMEM_BYTES  (128 * 129 * 4 + 256)

template <int EPI, bool BLO, bool WLO>
__global__ void __launch_bounds__(256, 1)
hmma_gemm(const __half* __restrict__ Ah, const __half* __restrict__ Al,
          const __half* __restrict__ Bh, const __half* __restrict__ Bl,
          const float* __restrict__ bias, float* __restrict__ Cf,
          __half* __restrict__ Ch, __half* __restrict__ Cl,
          int K, int lda, int ldb, int ldc,
          long sA, long sB, long sC, float alpha)
{
    extern __shared__ char smem_raw[];
    const uint32_t raw32 = smem_u32(smem_raw);
    const uint32_t sbase = (raw32 + 127) & ~127u;
    char* smem_al = smem_raw + (sbase - raw32);

    constexpr int NT = BLO ? 4 : 3;               // tiles per stage
    constexpr int STAGE_BYTES = NT * TILE_BYTES;

    const int tid = threadIdx.x;
    const int w = tid >> 5, l = tid & 31;
    const int m0 = blockIdx.y * BM;
    const int n0 = blockIdx.x * BN;
    const int z = blockIdx.z;

    const __half* srcs[4] = {Ah + z * sA, Al + z * sA, Bh + z * sB,
                             BLO ? (Bl + z * sB) : (Bh + z * sB)};
    const int rbs[4] = {m0, m0, n0, n0};
    const int lds_[4] = {lda, lda, ldb, ldb};

    const int NC = K / BK;

    auto load_stage = [&](int c) {
        const uint32_t stg = sbase + (c & 1) * STAGE_BYTES;
        #pragma unroll
        for (int i = 0; i < 2 * NT; i++) {
            int id = tid + i * 256;
            int t = id >> 9, rem = id & 511, row = rem >> 2, ch = rem & 3;
            const __half* g = srcs[t] + (long)(rbs[t] + row) * lds_[t] + (long)c * BK + ch * 8;
            uint32_t sa = stg + t * TILE_BYTES + row * 64 + ((ch ^ ((row >> 1) & 3)) << 4);
            cp16(sa, g);
        }
        asm volatile("cp.async.commit_group;" ::: "memory");
    };

    float acc[4][4][4] = {};
    const int wm = (w & 1) * 64;   // warp m-offset
    const int wn = (w >> 1) * 32;  // warp n-offset
    const int matI = l >> 3, rim = l & 7;

    load_stage(0);
    load_stage(1);

    for (int c = 0; c < NC; c++) {
        asm volatile("cp.async.wait_group 1;" ::: "memory");
        __syncthreads();
        const uint32_t stg = sbase + (c & 1) * STAGE_BYTES;

        #pragma unroll
        for (int kk = 0; kk < 2; kk++) {   // two k16 halves of the 32-wide chunk
            uint32_t fAh[4][4], fAl[4][4];
            #pragma unroll
            for (int mi = 0; mi < 4; mi++) {
                int row = wm + mi * 16 + rim + (matI & 1) * 8;
                int ch = kk * 2 + (matI >> 1);
                uint32_t off = row * 64 + ((ch ^ ((row >> 1) & 3)) << 4);
                ldsm_x4(fAh[mi], stg + off);
                ldsm_x4(fAl[mi], stg + TILE_BYTES + off);
            }
            uint32_t fBh[2][4], fBl[2][4];
            #pragma unroll
            for (int p = 0; p < 2; p++) {
                int n = wn + p * 16 + (matI >> 1) * 8 + rim;
                int ch = kk * 2 + (matI & 1);
                uint32_t off = n * 64 + ((ch ^ ((n >> 1) & 3)) << 4);
                ldsm_x4(fBh[p], stg + 2 * TILE_BYTES + off);
                if (BLO) ldsm_x4(fBl[p], stg + 3 * TILE_BYTES + off);
            }
            #pragma unroll
            for (int mi = 0; mi < 4; mi++)
                #pragma unroll
                for (int ni = 0; ni < 4; ni++) {
                    const uint32_t* bh = &fBh[ni >> 1][(ni & 1) * 2];
                    hmma(acc[mi][ni], fAh[mi], bh);
                    hmma(acc[mi][ni], fAl[mi], bh);
                    if (BLO) {
                        const uint32_t* bl = &fBl[ni >> 1][(ni & 1) * 2];
                        hmma(acc[mi][ni], fAh[mi], bl);
                    }
                }
        }
        __syncthreads();
        if (c + 2 < NC) load_stage(c + 2);
        else asm volatile("cp.async.commit_group;" ::: "memory");
    }
    asm volatile("cp.async.wait_group 0;" ::: "memory");
    __syncthreads();

    // ---------------- epilogue: regs -> SMEM stage -> coalesced GMEM ----------------
    float* sf = reinterpret_cast<float*>(smem_al);   // [128][129]
    const int r_ = l >> 2, cq = (l & 3) * 2;

    #pragma unroll
    for (int mi = 0; mi < 4; mi++)
        #pragma unroll
        for (int ni = 0; ni < 4; ni++) {
            int m = wm + mi * 16 + r_;
            int n = wn + ni * 8 + cq;
            float b0 = 0.f, b1 = 0.f;
            if (EPI != 2) { b0 = bias[n0 + n]; b1 = bias[n0 + n + 1]; }
            float v00 = acc[mi][ni][0] * alpha + b0;
            float v01 = acc[mi][ni][1] * alpha + b1;
            float v10 = acc[mi][ni][2] * alpha + b0;
            float v11 = acc[mi][ni][3] * alpha + b1;
            if (EPI == 1) {
                sf[n * 129 + m] = v00;       sf[(n + 1) * 129 + m] = v01;
                sf[n * 129 + m + 8] = v10;   sf[(n + 1) * 129 + m + 8] = v11;
            } else {
                sf[m * 129 + n] = v00;       sf[m * 129 + n + 1] = v01;
                sf[(m + 8) * 129 + n] = v10; sf[(m + 8) * 129 + n + 1] = v11;
            }
        }
    __syncthreads();

    if (EPI == 2) {
        float* Cb = Cf + z * sC;
        #pragma unroll
        for (int i = 0; i < 16; i++) {
            int idx = (tid + i * 256) << 2;
            int row = idx >> 7, col = idx & 127;
            const float* p = &sf[row * 129 + col];
            float4 v = make_float4(p[0], p[1], p[2], p[3]);
            *reinterpret_cast<float4*>(Cb + (long)(m0 + row) * ldc + n0 + col) = v;
        }
    } else {
        #pragma unroll
        for (int i = 0; i < 16; i++) {
            int idx = (tid + i * 256) << 2;
            int row = idx >> 7, col = idx & 127;
            const float* p = &sf[row * 129 + col];
            uint32_t hp[2], lp[2];
            #pragma unroll
            for (int q = 0; q < 2; q++) {
                float v0 = p[2 * q], v1 = p[2 * q + 1];
                __half h0 = __float2half_rn(v0), h1 = __float2half_rn(v1);
                __half2 H = __halves2half2(h0, h1);
                hp[q] = *reinterpret_cast<uint32_t*>(&H);
                if (WLO) {
                    __half l0 = __float2half_rn(v0 - __half2float(h0));
                    __half l1 = __float2half_rn(v1 - __half2float(h1));
                    __half2 L = __halves2half2(l0, l1);
                    lp[q] = *reinterpret_cast<uint32_t*>(&L);
                }
            }
            long dst = (EPI == 0) ? ((long)(m0 + row) * ldc + n0 + col)
                                  : ((long)(n0 + row) * ldc + m0 + col);
            *reinterpret_cast<uint2*>(Ch + dst) = make_uint2(hp[0], hp[1]);
            if (WLO) *reinterpret_cast<uint2*>(Cl + dst) = make_uint2(lp[0], lp[1]);
        }
    }
}

// ======================= fp32 -> fp16 hi/lo conversion =======================
__global__ void cvt_kernel(const float* __restrict__ in, __half* __restrict__ h,
                           __half* __restrict__ l, int n)
{
    int i = blockIdx.x * blockDim.x + threadIdx.x;
    if (i < n) {
        float v = in[i];
        __half a = __float2half_rn(v);
        h[i] = a;
        l[i] = __float2half_rn(v - __half2float(a));
    }
}

// ======================= softmax (f32 in place + fp16 hi/lo out) =======================
__global__ void __launch_bounds__(256) softmax_kernel(
    float* __restrict__ att, __half* __restrict__ Ph, __half* __restrict__ Pl)
{
    const int S = 2048, NPT = 8;
    const long rowoff = (long)blockIdx.x * S;
    float* row = att + rowoff;
    const int t = threadIdx.x, lane = t & 31, warp = t >> 5;

    __shared__ float red_max[8], red_sum[8];

    float v[NPT];
    float vmax = -1e30f;
    #pragma unroll
    for (int i = 0; i < NPT; i++) { v[i] = row[t + i * 256]; vmax = fmaxf(vmax, v[i]); }
    #pragma unroll
    for (int o = 16; o > 0; o >>= 1) vmax = fmaxf(vmax, __shfl_xor_sync(~0u, vmax, o));
    if (lane == 0) red_max[warp] = vmax;
    __syncthreads();
    vmax = red_max[0];
    #pragma unroll
    for (int i = 1; i < 8; i++) vmax = fmaxf(vmax, red_max[i]);

    float sum = 0.f;
    #pragma unroll
    for (int i = 0; i < NPT; i++) { v[i] = __expf(v[i] - vmax); sum += v[i]; }
    #pragma unroll
    for (int o = 16; o > 0; o >>= 1) sum += __shfl_xor_sync(~0u, sum, o);
    if (lane == 0) red_sum[warp] = sum;
    __syncthreads();
    float tot = red_sum[0];
    #pragma unroll
    for (int i = 1; i < 8; i++) tot += red_sum[i];
    float inv = 1.0f / tot;

    #pragma unroll
    for (int i = 0; i < NPT; i++) {
        float p = v[i] * inv;
        long off = rowoff + t + i * 256;
        row[t + i * 256] = p;
        __half h = __float2half_rn(p);
        Ph[off] = h;
        Pl[off] = __float2half_rn(p - __half2float(h));
    }
}

// ======================= launch =======================
extern "C" void kernel_launch(void* const* d_in, const int* in_sizes, int n_in,
                              void* d_out, int out_size)
{
    const float* x  = (const float*)d_in[0];
    const float* Wq = (const float*)d_in[1];
    const float* bq = (const float*)d_in[2];
    const float* Wk = (const float*)d_in[3];
    const float* bk = (const float*)d_in[4];
    const float* Wv = (const float*)d_in[5];
    const float* bv = (const float*)d_in[6];

    const int B = 4, S = 2048, D = 512;
    float* att = (float*)d_out;
    float* wtd = att + (size_t)B * S * S;

    __half *Xh, *Xl, *Wh, *Wl, *Qh, *Ql, *Kh, *Vth, *Ph, *Pl;
    cudaGetSymbolAddress((void**)&Xh, g_Xh);   cudaGetSymbolAddress((void**)&Xl, g_Xl);
    cudaGetSymbolAddress((void**)&Wh, g_Wh);   cudaGetSymbolAddress((void**)&Wl, g_Wl);
    cudaGetSymbolAddress((void**)&Qh, g_Qh);   cudaGetSymbolAddress((void**)&Ql, g_Ql);
    cudaGetSymbolAddress((void**)&Kh, g_Kh);
    cudaGetSymbolAddress((void**)&Vth, g_Vth);
    cudaGetSymbolAddress((void**)&Ph, g_Ph);   cudaGetSymbolAddress((void**)&Pl, g_Pl);

    cudaFuncSetAttribute(hmma_gemm<0, true, true>,  cudaFuncAttributeMaxDynamicSharedMemorySize, SMEM_BYTES);
    cudaFuncSetAttribute(hmma_gemm<0, true, false>, cudaFuncAttributeMaxDynamicSharedMemorySize, SMEM_BYTES);
    cudaFuncSetAttribute(hmma_gemm<1, true, false>, cudaFuncAttributeMaxDynamicSharedMemorySize, SMEM_BYTES);
    cudaFuncSetAttribute(hmma_gemm<2, false, false>,cudaFuncAttributeMaxDynamicSharedMemorySize, SMEM_BYTES);

    const int NX = B * S * D;          // 4.19M
    const int NW = D * D;              // 262144
    cvt_kernel<<<(NX + 511) / 512, 512>>>(x, Xh, Xl, NX);
    cvt_kernel<<<(NW + 511) / 512, 512>>>(Wq, Wh, Wl, NW);
    cvt_kernel<<<(NW + 511) / 512, 512>>>(Wk, Wh + NW, Wl + NW, NW);
    cvt_kernel<<<(NW + 511) / 512, 512>>>(Wv, Wh + 2 * NW, Wl + 2 * NW, NW);

    dim3 blk(256);

    // Q projection (hi+lo out), K projection (hi only), V projection (hi only, transposed)
    dim3 gproj(D / BN, (B * S) / BM, 1);
    hmma_gemm<0, true, true><<<gproj, blk, SMEM_BYTES>>>(
        Xh, Xl, Wh, Wl, bq, nullptr, Qh, Ql, D, D, D, D, 0, 0, 0, 1.0f);
    hmma_gemm<0, true, false><<<gproj, blk, SMEM_BYTES>>>(
        Xh, Xl, Wh + NW, Wl + NW, bk, nullptr, Kh, nullptr, D, D, D, D, 0, 0, 0, 1.0f);
    hmma_gemm<1, true, false><<<gproj, blk, SMEM_BYTES>>>(
        Xh, Xl, Wh + 2 * NW, Wl + 2 * NW, bv, nullptr, Vth, nullptr, D, D, D, 8192, 0, 0, 0, 1.0f);

    // scores: att[b] = Q[b] @ K[b]^T * scale   (2-term: Kl dropped)
    const float scale = 1.0f / sqrtf((float)D);
    dim3 gsc(S / BN, S / BM, B);
    hmma_gemm<2, false, false><<<gsc, blk, SMEM_BYTES>>>(
        Qh, Ql, Kh, nullptr, nullptr, att, nullptr, nullptr,
        D, D, D, S, (long)S * D, (long)S * D, (long)S * S, scale);

    // softmax (f32 in place into d_out, fp16 hi/lo for next GEMM)
    softmax_kernel<<<B * S, 256>>>(att, Ph, Pl);

    // weighted: wtd[b] = P[b] @ V[b]   (2-term: Vl dropped; Vt is [512, 8192])
    dim3 gw(D / BN, S / BM, B);
    hmma_gemm<2, false, false><<<gw, blk, SMEM_BYTES>>>(
        Ph, Pl, Vth, nullptr, nullptr, wtd, nullptr, nullptr,
        S, S, 8192, D, (long)S * S, (long)S, (long)S * D, 1.0f);
}

// round 5
// speedup vs baseline: 4.3987x; 1.2770x over previous
#include <cuda_runtime.h>
#include <cuda_fp16.h>
#include <math.h>
#include <stdint.h>

// ======================= scratch (static, allocation-free) =======================
static __device__ __half g_Xh[8192UL * 512], g_Xl[8192UL * 512];
static __device__ __half g_Wh[3UL * 512 * 512];
static __device__ __half g_Qh[8192UL * 512];
static __device__ __half g_Kh[8192UL * 512];
static __device__ __half g_Vth[512UL * 8192];
static __device__ __half g_Ph[4UL * 2048 * 2048];

// ======================= helpers (base ISA: sm_80/75 features only) =======================
__device__ __forceinline__ uint32_t smem_u32(const void* p) {
    uint32_t a;
    asm("{ .reg .u64 t; cvta.to.shared.u64 t, %1; cvt.u32.u64 %0, t; }" : "=r"(a) : "l"(p));
    return a;
}
__device__ __forceinline__ void ldsm_x4(uint32_t r[4], uint32_t addr) {
    asm volatile("ldmatrix.sync.aligned.m8n8.x4.shared.b16 {%0,%1,%2,%3}, [%4];"
                 : "=r"(r[0]), "=r"(r[1]), "=r"(r[2]), "=r"(r[3]) : "r"(addr));
}
__device__ __forceinline__ void hmma(float* c, const uint32_t* a, const uint32_t* b) {
    asm volatile(
        "mma.sync.aligned.m16n8k16.row.col.f32.f16.f16.f32 "
        "{%0,%1,%2,%3}, {%4,%5,%6,%7}, {%8,%9}, {%0,%1,%2,%3};"
        : "+f"(c[0]), "+f"(c[1]), "+f"(c[2]), "+f"(c[3])
        : "r"(a[0]), "r"(a[1]), "r"(a[2]), "r"(a[3]), "r"(b[0]), "r"(b[1]));
}
__device__ __forceinline__ void cp16(uint32_t s, const void* g) {
    asm volatile("cp.async.cg.shared.global [%0], [%1], 16;" :: "r"(s), "l"(g) : "memory");
}

// ======================= HMMA GEMM =======================
// D[m,n] = alpha * sum_k A[m,k]*B[n,k] (+ bias[n])
//   terms: Ah*Bh always, + Al*Bh iff ALO  (A hi/lo compensation)
// EPI 0: fp16 out at [(m0+r)*ldc + n0+c]  (+bias)            [Q/K proj]
// EPI 1: fp16 out at [(n0+r)*ldc + m0+c]  (+bias, transposed) [V proj]
// EPI 2: f32 out at [(m0+r)*ldc + n0+c]   (*alpha)            [scores / weighted]
#define BM 128
#define BN 128
#define BK 32
#define TILE_BYTES  (128 * 64)        // one 128x32 fp16 tile, 64B rows
#define SMEM_BYTES  (128 * 129 * 4 + 256)

template <int EPI, bool ALO>
__global__ void __launch_bounds__(256, 1)
hmma_gemm(const __half* __restrict__ Ah, const __half* __restrict__ Al,
          const __half* __restrict__ Bh,
          const float* __restrict__ bias, float* __restrict__ Cf,
          __half* __restrict__ Ch,
          int K, int lda, int ldb, int ldc,
          long sA, long sB, long sC, float alpha)
{
    extern __shared__ char smem_raw[];
    const uint32_t raw32 = smem_u32(smem_raw);
    const uint32_t sbase = (raw32 + 127) & ~127u;
    char* smem_al = smem_raw + (sbase - raw32);

    constexpr int NT = ALO ? 3 : 2;               // tiles per stage: Ah [, Al], Bh
    constexpr int STAGE_BYTES = NT * TILE_BYTES;
    constexpr int BT = ALO ? 2 : 1;               // Bh tile index

    const int tid = threadIdx.x;
    const int w = tid >> 5, l = tid & 31;
    const int m0 = blockIdx.y * BM;
    const int n0 = blockIdx.x * BN;
    const int z = blockIdx.z;

    const __half* srcs[NT];
    int rbs[NT], lds_[NT];
    srcs[0] = Ah + z * sA; rbs[0] = m0; lds_[0] = lda;
    if (ALO) { srcs[1] = Al + z * sA; rbs[1] = m0; lds_[1] = lda; }
    srcs[BT] = Bh + z * sB; rbs[BT] = n0; lds_[BT] = ldb;

    const int NC = K / BK;

    auto load_stage = [&](int c) {
        const uint32_t stg = sbase + (c & 1) * STAGE_BYTES;
        #pragma unroll
        for (int i = 0; i < 2 * NT; i++) {
            int id = tid + i * 256;
            int t = id >> 9, rem = id & 511, row = rem >> 2, ch = rem & 3;
            const __half* g = srcs[t] + (long)(rbs[t] + row) * lds_[t] + (long)c * BK + ch * 8;
            uint32_t sa = stg + t * TILE_BYTES + row * 64 + ((ch ^ ((row >> 1) & 3)) << 4);
            cp16(sa, g);
        }
        asm volatile("cp.async.commit_group;" ::: "memory");
    };

    float acc[4][4][4] = {};
    const int wm = (w & 1) * 64;   // warp m-offset
    const int wn = (w >> 1) * 32;  // warp n-offset
    const int matI = l >> 3, rim = l & 7;

    load_stage(0);
    load_stage(1);

    for (int c = 0; c < NC; c++) {
        asm volatile("cp.async.wait_group 1;" ::: "memory");
        __syncthreads();
        const uint32_t stg = sbase + (c & 1) * STAGE_BYTES;

        #pragma unroll
        for (int kk = 0; kk < 2; kk++) {   // two k16 halves of the 32-wide chunk
            uint32_t fAh[4][4], fAl[4][4];
            #pragma unroll
            for (int mi = 0; mi < 4; mi++) {
                int row = wm + mi * 16 + rim + (matI & 1) * 8;
                int ch = kk * 2 + (matI >> 1);
                uint32_t off = row * 64 + ((ch ^ ((row >> 1) & 3)) << 4);
                ldsm_x4(fAh[mi], stg + off);
                if (ALO) ldsm_x4(fAl[mi], stg + TILE_BYTES + off);
            }
            uint32_t fBh[2][4];
            #pragma unroll
            for (int p = 0; p < 2; p++) {
                int n = wn + p * 16 + (matI >> 1) * 8 + rim;
                int ch = kk * 2 + (matI & 1);
                uint32_t off = n * 64 + ((ch ^ ((n >> 1) & 3)) << 4);
                ldsm_x4(fBh[p], stg + BT * TILE_BYTES + off);
            }
            #pragma unroll
            for (int mi = 0; mi < 4; mi++)
                #pragma unroll
                for (int ni = 0; ni < 4; ni++) {
                    const uint32_t* bh = &fBh[ni >> 1][(ni & 1) * 2];
                    hmma(acc[mi][ni], fAh[mi], bh);
                    if (ALO) hmma(acc[mi][ni], fAl[mi], bh);
                }
        }
        __syncthreads();
        if (c + 2 < NC) load_stage(c + 2);
        else asm volatile("cp.async.commit_group;" ::: "memory");
    }
    asm volatile("cp.async.wait_group 0;" ::: "memory");
    __syncthreads();

    // ---------------- epilogue: regs -> SMEM stage -> coalesced GMEM ----------------
    float* sf = reinterpret_cast<float*>(smem_al);   // [128][129]
    const int r_ = l >> 2, cq = (l & 3) * 2;

    #pragma unroll
    for (int mi = 0; mi < 4; mi++)
        #pragma unroll
        for (int ni = 0; ni < 4; ni++) {
            int m = wm + mi * 16 + r_;
            int n = wn + ni * 8 + cq;
            float b0 = 0.f, b1 = 0.f;
            if (EPI != 2) { b0 = bias[n0 + n]; b1 = bias[n0 + n + 1]; }
            float v00 = acc[mi][ni][0] * alpha + b0;
            float v01 = acc[mi][ni][1] * alpha + b1;
            float v10 = acc[mi][ni][2] * alpha + b0;
            float v11 = acc[mi][ni][3] * alpha + b1;
            if (EPI == 1) {
                sf[n * 129 + m] = v00;       sf[(n + 1) * 129 + m] = v01;
                sf[n * 129 + m + 8] = v10;   sf[(n + 1) * 129 + m + 8] = v11;
            } else {
                sf[m * 129 + n] = v00;       sf[m * 129 + n + 1] = v01;
                sf[(m + 8) * 129 + n] = v10; sf[(m + 8) * 129 + n + 1] = v11;
            }
        }
    __syncthreads();

    if (EPI == 2) {
        float* Cb = Cf + z * sC;
        #pragma unroll
        for (int i = 0; i < 16; i++) {
            int idx = (tid + i * 256) << 2;
            int row = idx >> 7, col = idx & 127;
            const float* p = &sf[row * 129 + col];
            float4 v = make_float4(p[0], p[1], p[2], p[3]);
            *reinterpret_cast<float4*>(Cb + (long)(m0 + row) * ldc + n0 + col) = v;
        }
    } else {
        #pragma unroll
        for (int i = 0; i < 16; i++) {
            int idx = (tid + i * 256) << 2;
            int row = idx >> 7, col = idx & 127;
            const float* p = &sf[row * 129 + col];
            uint32_t hp[2];
            #pragma unroll
            for (int q = 0; q < 2; q++) {
                __half2 H = __halves2half2(__float2half_rn(p[2 * q]),
                                           __float2half_rn(p[2 * q + 1]));
                hp[q] = *reinterpret_cast<uint32_t*>(&H);
            }
            long dst = (EPI == 0) ? ((long)(m0 + row) * ldc + n0 + col)
                                  : ((long)(n0 + row) * ldc + m0 + col);
            *reinterpret_cast<uint2*>(Ch + dst) = make_uint2(hp[0], hp[1]);
        }
    }
}

// ======================= fp32 -> fp16 conversions =======================
__global__ void cvt2_kernel(const float* __restrict__ in, __half* __restrict__ h,
                            __half* __restrict__ l, int n)
{
    int i = blockIdx.x * blockDim.x + threadIdx.x;
    if (i < n) {
        float v = in[i];
        __half a = __float2half_rn(v);
        h[i] = a;
        l[i] = __float2half_rn(v - __half2float(a));
    }
}
__global__ void cvt1_kernel(const float* __restrict__ in, __half* __restrict__ h, int n)
{
    int i = blockIdx.x * blockDim.x + threadIdx.x;
    if (i < n) h[i] = __float2half_rn(in[i]);
}

// ======================= softmax (f32 in place + fp16 out) =======================
__global__ void __launch_bounds__(256) softmax_kernel(
    float* __restrict__ att, __half* __restrict__ Ph)
{
    const int S = 2048, NPT = 8;
    const long rowoff = (long)blockIdx.x * S;
    float* row = att + rowoff;
    const int t = threadIdx.x, lane = t & 31, warp = t >> 5;

    __shared__ float red_max[8], red_sum[8];

    float v[NPT];
    float vmax = -1e30f;
    #pragma unroll
    for (int i = 0; i < NPT; i++) { v[i] = row[t + i * 256]; vmax = fmaxf(vmax, v[i]); }
    #pragma unroll
    for (int o = 16; o > 0; o >>= 1) vmax = fmaxf(vmax, __shfl_xor_sync(~0u, vmax, o));
    if (lane == 0) red_max[warp] = vmax;
    __syncthreads();
    vmax = red_max[0];
    #pragma unroll
    for (int i = 1; i < 8; i++) vmax = fmaxf(vmax, red_max[i]);

    float sum = 0.f;
    #pragma unroll
    for (int i = 0; i < NPT; i++) { v[i] = __expf(v[i] - vmax); sum += v[i]; }
    #pragma unroll
    for (int o = 16; o > 0; o >>= 1) sum += __shfl_xor_sync(~0u, sum, o);
    if (lane == 0) red_sum[warp] = sum;
    __syncthreads();
    float tot = red_sum[0];
    #pragma unroll
    for (int i = 1; i < 8; i++) tot += red_sum[i];
    float inv = 1.0f / tot;

    #pragma unroll
    for (int i = 0; i < NPT; i++) {
        float p = v[i] * inv;
        row[t + i * 256] = p;
        Ph[rowoff + t + i * 256] = __float2half_rn(p);
    }
}

// ======================= launch =======================
extern "C" void kernel_launch(void* const* d_in, const int* in_sizes, int n_in,
                              void* d_out, int out_size)
{
    const float* x  = (const float*)d_in[0];
    const float* Wq = (const float*)d_in[1];
    const float* bq = (const float*)d_in[2];
    const float* Wk = (const float*)d_in[3];
    const float* bk = (const float*)d_in[4];
    const float* Wv = (const float*)d_in[5];
    const float* bv = (const float*)d_in[6];

    const int B = 4, S = 2048, D = 512;
    float* att = (float*)d_out;
    float* wtd = att + (size_t)B * S * S;

    __half *Xh, *Xl, *Wh, *Qh, *Kh, *Vth, *Ph;
    cudaGetSymbolAddress((void**)&Xh, g_Xh);   cudaGetSymbolAddress((void**)&Xl, g_Xl);
    cudaGetSymbolAddress((void**)&Wh, g_Wh);
    cudaGetSymbolAddress((void**)&Qh, g_Qh);
    cudaGetSymbolAddress((void**)&Kh, g_Kh);
    cudaGetSymbolAddress((void**)&Vth, g_Vth);
    cudaGetSymbolAddress((void**)&Ph, g_Ph);

    cudaFuncSetAttribute(hmma_gemm<0, true>,  cudaFuncAttributeMaxDynamicSharedMemorySize, SMEM_BYTES);
    cudaFuncSetAttribute(hmma_gemm<1, true>,  cudaFuncAttributeMaxDynamicSharedMemorySize, SMEM_BYTES);
    cudaFuncSetAttribute(hmma_gemm<2, false>, cudaFuncAttributeMaxDynamicSharedMemorySize, SMEM_BYTES);

    const int NX = B * S * D;          // 4.19M
    const int NW = D * D;              // 262144
    cvt2_kernel<<<(NX + 511) / 512, 512>>>(x, Xh, Xl, NX);
    cvt1_kernel<<<(NW + 511) / 512, 512>>>(Wq, Wh, NW);
    cvt1_kernel<<<(NW + 511) / 512, 512>>>(Wk, Wh + NW, NW);
    cvt1_kernel<<<(NW + 511) / 512, 512>>>(Wv, Wh + 2 * NW, NW);

    dim3 blk(256);

    // projections (2-term: XhWh + XlWh)
    dim3 gproj(D / BN, (B * S) / BM, 1);
    hmma_gemm<0, true><<<gproj, blk, SMEM_BYTES>>>(
        Xh, Xl, Wh, bq, nullptr, Qh, D, D, D, D, 0, 0, 0, 1.0f);
    hmma_gemm<0, true><<<gproj, blk, SMEM_BYTES>>>(
        Xh, Xl, Wh + NW, bk, nullptr, Kh, D, D, D, D, 0, 0, 0, 1.0f);
    hmma_gemm<1, true><<<gproj, blk, SMEM_BYTES>>>(
        Xh, Xl, Wh + 2 * NW, bv, nullptr, Vth, D, D, D, 8192, 0, 0, 0, 1.0f);

    // scores: att[b] = Q[b] @ K[b]^T * scale   (1-term)
    const float scale = 1.0f / sqrtf((float)D);
    dim3 gsc(S / BN, S / BM, B);
    hmma_gemm<2, false><<<gsc, blk, SMEM_BYTES>>>(
        Qh, nullptr, Kh, nullptr, att, nullptr,
        D, D, D, S, (long)S * D, (long)S * D, (long)S * S, scale);

    // softmax (f32 in place into d_out, fp16 for next GEMM)
    softmax_kernel<<<B * S, 256>>>(att, Ph);

    // weighted: wtd[b] = P[b] @ V[b]   (1-term; Vt is [512, 8192])
    dim3 gw(D / BN, S / BM, B);
    hmma_gemm<2, false><<<gw, blk, SMEM_BYTES>>>(
        Ph, nullptr, Vth, nullptr, wtd, nullptr,
        S, S, 8192, D, (long)S * S, (long)S, (long)S * D, 1.0f);
}

// round 6
// speedup vs baseline: 4.9973x; 1.1361x over previous
#include <cuda_runtime.h>
#include <cuda_fp16.h>
#include <math.h>
#include <stdint.h>

// ======================= scratch (static, allocation-free) =======================
static __device__ __half g_Xh[8192UL * 512], g_Xl[8192UL * 512];
static __device__ __half g_Wh[3UL * 512 * 512];
static __device__ __half g_Qh[8192UL * 512];
static __device__ __half g_Kh[8192UL * 512];
static __device__ __half g_Vth[512UL * 8192];
static __device__ __half g_Ph[4UL * 2048 * 2048];

// ======================= helpers (base ISA: sm_80/75 features only) =======================
__device__ __forceinline__ uint32_t smem_u32(const void* p) {
    uint32_t a;
    asm("{ .reg .u64 t; cvta.to.shared.u64 t, %1; cvt.u32.u64 %0, t; }" : "=r"(a) : "l"(p));
    return a;
}
__device__ __forceinline__ void ldsm_x4(uint32_t r[4], uint32_t addr) {
    asm volatile("ldmatrix.sync.aligned.m8n8.x4.shared.b16 {%0,%1,%2,%3}, [%4];"
                 : "=r"(r[0]), "=r"(r[1]), "=r"(r[2]), "=r"(r[3]) : "r"(addr));
}
__device__ __forceinline__ void hmma(float* c, const uint32_t* a, const uint32_t* b) {
    asm volatile(
        "mma.sync.aligned.m16n8k16.row.col.f32.f16.f16.f32 "
        "{%0,%1,%2,%3}, {%4,%5,%6,%7}, {%8,%9}, {%0,%1,%2,%3};"
        : "+f"(c[0]), "+f"(c[1]), "+f"(c[2]), "+f"(c[3])
        : "r"(a[0]), "r"(a[1]), "r"(a[2]), "r"(a[3]), "r"(b[0]), "r"(b[1]));
}
__device__ __forceinline__ void cp16(uint32_t s, const void* g) {
    asm volatile("cp.async.cg.shared.global [%0], [%1], 16;" :: "r"(s), "l"(g) : "memory");
}

// =============================================================================
// proj GEMM: 128x128 tile, warp 64x32, 2-term (Ah*B + Al*B), 3-stage pipeline
// EPI 0: fp16 out [(m0+r)*ldc + n0+c] (+bias)        [Q/K proj]
// EPI 1: fp16 out [(n0+r)*ldc + m0+c] (+bias, transposed) [V proj]
// =============================================================================
#define PTILE 8192                       // one 128x32 fp16 tile
#define PSTG  (3 * PTILE)                // Ah, Al, B per stage
#define SMEM_P (3 * PSTG + 256)          // 3 stages (73984); epi 66KB fits inside

template <int EPI>
__global__ void __launch_bounds__(256, 1)
proj_gemm(const __half* __restrict__ Ah, const __half* __restrict__ Al,
          const __half* __restrict__ Bh,
          const float* __restrict__ bias, __half* __restrict__ Ch,
          int K, int lda, int ldb, int ldc)
{
    extern __shared__ char smem_raw[];
    const uint32_t raw32 = smem_u32(smem_raw);
    const uint32_t sbase = (raw32 + 127) & ~127u;
    char* smem_al = smem_raw + (sbase - raw32);

    const int tid = threadIdx.x;
    const int w = tid >> 5, l = tid & 31;
    const int m0 = blockIdx.y * 128;
    const int n0 = blockIdx.x * 128;

    const __half* srcs[3] = {Ah, Al, Bh};
    const int rbs[3] = {m0, m0, n0};
    const int lds_[3] = {lda, lda, ldb};

    const int NC = K / 32;

    auto load_stage = [&](int c) {
        const uint32_t stg = sbase + (c % 3) * PSTG;
        #pragma unroll
        for (int i = 0; i < 6; i++) {
            int id = tid + i * 256;
            int t = id >> 9, rem = id & 511, row = rem >> 2, ch = rem & 3;
            const __half* g = srcs[t] + (long)(rbs[t] + row) * lds_[t] + (long)c * 32 + ch * 8;
            uint32_t sa = stg + t * PTILE + row * 64 + ((ch ^ ((row >> 1) & 3)) << 4);
            cp16(sa, g);
        }
        asm volatile("cp.async.commit_group;" ::: "memory");
    };

    float acc[4][4][4] = {};
    const int wm = (w & 1) * 64;
    const int wn = (w >> 1) * 32;
    const int matI = l >> 3, rim = l & 7;

    load_stage(0);
    load_stage(1);

    for (int c = 0; c < NC; c++) {
        asm volatile("cp.async.wait_group 1;" ::: "memory");
        __syncthreads();
        if (c + 2 < NC) load_stage(c + 2);
        else asm volatile("cp.async.commit_group;" ::: "memory");

        const uint32_t stg = sbase + (c % 3) * PSTG;
        #pragma unroll
        for (int kk = 0; kk < 2; kk++) {
            uint32_t fAh[4][4], fAl[4][4];
            #pragma unroll
            for (int mi = 0; mi < 4; mi++) {
                int row = wm + mi * 16 + rim + (matI & 1) * 8;
                int ch = kk * 2 + (matI >> 1);
                uint32_t off = row * 64 + ((ch ^ ((row >> 1) & 3)) << 4);
                ldsm_x4(fAh[mi], stg + off);
                ldsm_x4(fAl[mi], stg + PTILE + off);
            }
            uint32_t fB[2][4];
            #pragma unroll
            for (int p = 0; p < 2; p++) {
                int n = wn + p * 16 + (matI >> 1) * 8 + rim;
                int ch = kk * 2 + (matI & 1);
                uint32_t off = n * 64 + ((ch ^ ((n >> 1) & 3)) << 4);
                ldsm_x4(fB[p], stg + 2 * PTILE + off);
            }
            #pragma unroll
            for (int mi = 0; mi < 4; mi++)
                #pragma unroll
                for (int ni = 0; ni < 4; ni++) {
                    const uint32_t* b = &fB[ni >> 1][(ni & 1) * 2];
                    hmma(acc[mi][ni], fAh[mi], b);
                    hmma(acc[mi][ni], fAl[mi], b);
                }
        }
    }
    asm volatile("cp.async.wait_group 0;" ::: "memory");
    __syncthreads();

    // epilogue: regs -> SMEM -> coalesced fp16 GMEM
    float* sf = reinterpret_cast<float*>(smem_al);   // [128][129]
    const int r_ = l >> 2, cq = (l & 3) * 2;

    #pragma unroll
    for (int mi = 0; mi < 4; mi++)
        #pragma unroll
        for (int ni = 0; ni < 4; ni++) {
            int m = wm + mi * 16 + r_;
            int n = wn + ni * 8 + cq;
            float b0 = bias[n0 + n], b1 = bias[n0 + n + 1];
            float v00 = acc[mi][ni][0] + b0, v01 = acc[mi][ni][1] + b1;
            float v10 = acc[mi][ni][2] + b0, v11 = acc[mi][ni][3] + b1;
            if (EPI == 1) {
                sf[n * 129 + m] = v00;       sf[(n + 1) * 129 + m] = v01;
                sf[n * 129 + m + 8] = v10;   sf[(n + 1) * 129 + m + 8] = v11;
            } else {
                sf[m * 129 + n] = v00;       sf[m * 129 + n + 1] = v01;
                sf[(m + 8) * 129 + n] = v10; sf[(m + 8) * 129 + n + 1] = v11;
            }
        }
    __syncthreads();

    #pragma unroll
    for (int i = 0; i < 16; i++) {
        int idx = (tid + i * 256) << 2;
        int row = idx >> 7, col = idx & 127;
        const float* p = &sf[row * 129 + col];
        uint32_t hp[2];
        #pragma unroll
        for (int q = 0; q < 2; q++) {
            __half2 H = __halves2half2(__float2half_rn(p[2 * q]), __float2half_rn(p[2 * q + 1]));
            hp[q] = *reinterpret_cast<uint32_t*>(&H);
        }
        long dst = (EPI == 0) ? ((long)(m0 + row) * ldc + n0 + col)
                              : ((long)(n0 + row) * ldc + m0 + col);
        *reinterpret_cast<uint2*>(Ch + dst) = make_uint2(hp[0], hp[1]);
    }
}

// =============================================================================
// big GEMM: 128x256 tile, warp 64x64, 1-term, f32 out, 3-stage pipeline
// C[m,n] = alpha * sum_k A[m,k]*B[n,k]
// =============================================================================
#define GSTG  24576                       // A 8KB + B 16KB per stage
#define SMEM_G (128 * 257 * 4 + 256)      // 131840 > 3*GSTG (73728)

__global__ void __launch_bounds__(256, 1)
big_gemm(const __half* __restrict__ A, const __half* __restrict__ B,
         float* __restrict__ Cf,
         int K, int lda, int ldb, int ldc,
         long sA, long sB, long sC, float alpha)
{
    extern __shared__ char smem_raw[];
    const uint32_t raw32 = smem_u32(smem_raw);
    const uint32_t sbase = (raw32 + 127) & ~127u;
    char* smem_al = smem_raw + (sbase - raw32);

    const int tid = threadIdx.x;
    const int w = tid >> 5, l = tid & 31;
    const int m0 = blockIdx.y * 128;
    const int n0 = blockIdx.x * 256;
    const int z = blockIdx.z;

    const __half* Ab = A + z * sA;
    const __half* Bb = B + z * sB;

    const int NC = K / 32;

    auto load_stage = [&](int c) {
        const uint32_t stg = sbase + (c % 3) * GSTG;
        #pragma unroll
        for (int i = 0; i < 6; i++) {
            int id = tid + i * 256;
            int t = id >> 9, rem = id & 511, row = rem >> 2, ch = rem & 3;
            const __half* g = (t == 0)
                ? Ab + (long)(m0 + row) * lda + (long)c * 32 + ch * 8
                : Bb + (long)(n0 + (t - 1) * 128 + row) * ldb + (long)c * 32 + ch * 8;
            uint32_t sa = stg + t * 8192 + row * 64 + ((ch ^ ((row >> 1) & 3)) << 4);
            cp16(sa, g);
        }
        asm volatile("cp.async.commit_group;" ::: "memory");
    };

    float acc[4][8][4] = {};
    const int wm = (w & 1) * 64;      // 2 m-halves
    const int wn = (w >> 1) * 64;     // 4 n-quarters
    const int matI = l >> 3, rim = l & 7;

    load_stage(0);
    load_stage(1);

    for (int c = 0; c < NC; c++) {
        asm volatile("cp.async.wait_group 1;" ::: "memory");
        __syncthreads();
        if (c + 2 < NC) load_stage(c + 2);
        else asm volatile("cp.async.commit_group;" ::: "memory");

        const uint32_t stg = sbase + (c % 3) * GSTG;
        const uint32_t bbase = stg + 8192;
        #pragma unroll
        for (int kk = 0; kk < 2; kk++) {
            uint32_t fA[4][4];
            #pragma unroll
            for (int mi = 0; mi < 4; mi++) {
                int row = wm + mi * 16 + rim + (matI & 1) * 8;
                int ch = kk * 2 + (matI >> 1);
                ldsm_x4(fA[mi], stg + row * 64 + ((ch ^ ((row >> 1) & 3)) << 4));
            }
            uint32_t fB[4][4];
            #pragma unroll
            for (int p = 0; p < 4; p++) {
                int n = wn + p * 16 + (matI >> 1) * 8 + rim;
                int ch = kk * 2 + (matI & 1);
                ldsm_x4(fB[p], bbase + n * 64 + ((ch ^ ((n >> 1) & 3)) << 4));
            }
            #pragma unroll
            for (int mi = 0; mi < 4; mi++)
                #pragma unroll
                for (int ni = 0; ni < 8; ni++)
                    hmma(acc[mi][ni], fA[mi], &fB[ni >> 1][(ni & 1) * 2]);
        }
    }
    asm volatile("cp.async.wait_group 0;" ::: "memory");
    __syncthreads();

    // epilogue: regs -> SMEM [128][257] -> coalesced f32 GMEM
    float* sf = reinterpret_cast<float*>(smem_al);
    const int r_ = l >> 2, cq = (l & 3) * 2;

    #pragma unroll
    for (int mi = 0; mi < 4; mi++)
        #pragma unroll
        for (int ni = 0; ni < 8; ni++) {
            int m = wm + mi * 16 + r_;
            int n = wn + ni * 8 + cq;
            sf[m * 257 + n] = acc[mi][ni][0] * alpha;
            sf[m * 257 + n + 1] = acc[mi][ni][1] * alpha;
            sf[(m + 8) * 257 + n] = acc[mi][ni][2] * alpha;
            sf[(m + 8) * 257 + n + 1] = acc[mi][ni][3] * alpha;
        }
    __syncthreads();

    float* Cb = Cf + z * sC;
    #pragma unroll
    for (int i = 0; i < 32; i++) {
        int idx = (tid + i * 256) << 2;
        int row = idx >> 8, col = idx & 255;
        const float* p = &sf[row * 257 + col];
        float4 v = make_float4(p[0], p[1], p[2], p[3]);
        *reinterpret_cast<float4*>(Cb + (long)(m0 + row) * ldc + n0 + col) = v;
    }
}

// ======================= fp32 -> fp16 conversions =======================
__global__ void cvt2_kernel(const float* __restrict__ in, __half* __restrict__ h,
                            __half* __restrict__ l, int n)
{
    int i = blockIdx.x * blockDim.x + threadIdx.x;
    if (i < n) {
        float v = in[i];
        __half a = __float2half_rn(v);
        h[i] = a;
        l[i] = __float2half_rn(v - __half2float(a));
    }
}
__global__ void cvt1_kernel(const float* __restrict__ in, __half* __restrict__ h, int n)
{
    int i = blockIdx.x * blockDim.x + threadIdx.x;
    if (i < n) h[i] = __float2half_rn(in[i]);
}

// ======================= softmax (f32 in place + fp16 out) =======================
__global__ void __launch_bounds__(256) softmax_kernel(
    float* __restrict__ att, __half* __restrict__ Ph)
{
    const int S = 2048, NPT = 8;
    const long rowoff = (long)blockIdx.x * S;
    float* row = att + rowoff;
    const int t = threadIdx.x, lane = t & 31, warp = t >> 5;

    __shared__ float red_max[8], red_sum[8];

    float v[NPT];
    float vmax = -1e30f;
    #pragma unroll
    for (int i = 0; i < NPT; i++) { v[i] = row[t + i * 256]; vmax = fmaxf(vmax, v[i]); }
    #pragma unroll
    for (int o = 16; o > 0; o >>= 1) vmax = fmaxf(vmax, __shfl_xor_sync(~0u, vmax, o));
    if (lane == 0) red_max[warp] = vmax;
    __syncthreads();
    vmax = red_max[0];
    #pragma unroll
    for (int i = 1; i < 8; i++) vmax = fmaxf(vmax, red_max[i]);

    float sum = 0.f;
    #pragma unroll
    for (int i = 0; i < NPT; i++) { v[i] = __expf(v[i] - vmax); sum += v[i]; }
    #pragma unroll
    for (int o = 16; o > 0; o >>= 1) sum += __shfl_xor_sync(~0u, sum, o);
    if (lane == 0) red_sum[warp] = sum;
    __syncthreads();
    float tot = red_sum[0];
    #pragma unroll
    for (int i = 1; i < 8; i++) tot += red_sum[i];
    float inv = 1.0f / tot;

    #pragma unroll
    for (int i = 0; i < NPT; i++) {
        float p = v[i] * inv;
        row[t + i * 256] = p;
        Ph[rowoff + t + i * 256] = __float2half_rn(p);
    }
}

// ======================= launch =======================
extern "C" void kernel_launch(void* const* d_in, const int* in_sizes, int n_in,
                              void* d_out, int out_size)
{
    const float* x  = (const float*)d_in[0];
    const float* Wq = (const float*)d_in[1];
    const float* bq = (const float*)d_in[2];
    const float* Wk = (const float*)d_in[3];
    const float* bk = (const float*)d_in[4];
    const float* Wv = (const float*)d_in[5];
    const float* bv = (const float*)d_in[6];

    const int B = 4, S = 2048, D = 512;
    float* att = (float*)d_out;
    float* wtd = att + (size_t)B * S * S;

    __half *Xh, *Xl, *Wh, *Qh, *Kh, *Vth, *Ph;
    cudaGetSymbolAddress((void**)&Xh, g_Xh);   cudaGetSymbolAddress((void**)&Xl, g_Xl);
    cudaGetSymbolAddress((void**)&Wh, g_Wh);
    cudaGetSymbolAddress((void**)&Qh, g_Qh);
    cudaGetSymbolAddress((void**)&Kh, g_Kh);
    cudaGetSymbolAddress((void**)&Vth, g_Vth);
    cudaGetSymbolAddress((void**)&Ph, g_Ph);

    cudaFuncSetAttribute(proj_gemm<0>, cudaFuncAttributeMaxDynamicSharedMemorySize, SMEM_P);
    cudaFuncSetAttribute(proj_gemm<1>, cudaFuncAttributeMaxDynamicSharedMemorySize, SMEM_P);
    cudaFuncSetAttribute(big_gemm,     cudaFuncAttributeMaxDynamicSharedMemorySize, SMEM_G);

    const int NX = B * S * D;
    const int NW = D * D;
    cvt2_kernel<<<(NX + 511) / 512, 512>>>(x, Xh, Xl, NX);
    cvt1_kernel<<<(NW + 511) / 512, 512>>>(Wq, Wh, NW);
    cvt1_kernel<<<(NW + 511) / 512, 512>>>(Wk, Wh + NW, NW);
    cvt1_kernel<<<(NW + 511) / 512, 512>>>(Wv, Wh + 2 * NW, NW);

    dim3 blk(256);

    // projections (2-term)
    dim3 gproj(D / 128, (B * S) / 128, 1);
    proj_gemm<0><<<gproj, blk, SMEM_P>>>(Xh, Xl, Wh, bq, Qh, D, D, D, D);
    proj_gemm<0><<<gproj, blk, SMEM_P>>>(Xh, Xl, Wh + NW, bk, Kh, D, D, D, D);
    proj_gemm<1><<<gproj, blk, SMEM_P>>>(Xh, Xl, Wh + 2 * NW, bv, Vth, D, D, D, 8192);

    // scores: att[b] = Q[b] @ K[b]^T * scale
    const float scale = 1.0f / sqrtf((float)D);
    dim3 gsc(S / 256, S / 128, B);
    big_gemm<<<gsc, blk, SMEM_G>>>(Qh, Kh, att, D, D, D, S,
                                   (long)S * D, (long)S * D, (long)S * S, scale);

    // softmax
    softmax_kernel<<<B * S, 256>>>(att, Ph);

    // weighted: wtd[b] = P[b] @ V[b]  (Vt is [512, 8192], per-batch col offset b*2048)
    dim3 gw(D / 256, S / 128, B);
    big_gemm<<<gw, blk, SMEM_G>>>(Ph, Vth, wtd, S, S, 8192, D,
                                  (long)S * S, (long)S, (long)S * D, 1.0f);
}

// round 7
// speedup vs baseline: 5.8663x; 1.1739x over previous
#include <cuda_runtime.h>
#include <cuda_fp16.h>
#include <math.h>
#include <stdint.h>

// ======================= scratch (static, allocation-free) =======================
static __device__ __half g_Xh[8192UL * 512], g_Xl[8192UL * 512];
static __device__ __half g_Wh[3UL * 512 * 512];
static __device__ __half g_Qh[8192UL * 512];
static __device__ __half g_Kh[8192UL * 512];
static __device__ __half g_Vth[512UL * 8192];
static __device__ __half g_Ph[4UL * 2048 * 2048];

// ======================= helpers (base ISA: sm_80/75 features only) =======================
__device__ __forceinline__ uint32_t smem_u32(const void* p) {
    uint32_t a;
    asm("{ .reg .u64 t; cvta.to.shared.u64 t, %1; cvt.u32.u64 %0, t; }" : "=r"(a) : "l"(p));
    return a;
}
__device__ __forceinline__ void ldsm_x4(uint32_t r[4], uint32_t addr) {
    asm volatile("ldmatrix.sync.aligned.m8n8.x4.shared.b16 {%0,%1,%2,%3}, [%4];"
                 : "=r"(r[0]), "=r"(r[1]), "=r"(r[2]), "=r"(r[3]) : "r"(addr));
}
__device__ __forceinline__ void hmma(float* c, const uint32_t* a, const uint32_t* b) {
    asm volatile(
        "mma.sync.aligned.m16n8k16.row.col.f32.f16.f16.f32 "
        "{%0,%1,%2,%3}, {%4,%5,%6,%7}, {%8,%9}, {%0,%1,%2,%3};"
        : "+f"(c[0]), "+f"(c[1]), "+f"(c[2]), "+f"(c[3])
        : "r"(a[0]), "r"(a[1]), "r"(a[2]), "r"(a[3]), "r"(b[0]), "r"(b[1]));
}
__device__ __forceinline__ void cp16(uint32_t s, const void* g) {
    asm volatile("cp.async.cg.shared.global [%0], [%1], 16;" :: "r"(s), "l"(g) : "memory");
}

// =============================================================================
// fused QKV projection: C_sec = X @ Wsec^T + bsec, 2-term (Xh+Xl)
// grid.x = 1536/128 = 12 (section = n0g>>9), grid.y = 8192/128 = 64
// sec 0 -> Qh [8192,512], sec 1 -> Kh [8192,512], sec 2 -> Vth [512,8192] transposed
// =============================================================================
#define PTILE 8192                       // 128x32 fp16 tile
#define PSTG  (3 * PTILE)                // Xh, Xl, W tiles
#define SMEM_P (3 * PSTG + 256)          // 73984; epi 66048 fits

__global__ void __launch_bounds__(256, 2)
qkv_gemm(const __half* __restrict__ Xh, const __half* __restrict__ Xl,
         const __half* __restrict__ Wh,
         const float* __restrict__ bq, const float* __restrict__ bk,
         const float* __restrict__ bv,
         __half* __restrict__ Qh, __half* __restrict__ Kh, __half* __restrict__ Vth)
{
    extern __shared__ char smem_raw[];
    const uint32_t raw32 = smem_u32(smem_raw);
    const uint32_t sbase = (raw32 + 127) & ~127u;
    char* smem_al = smem_raw + (sbase - raw32);

    const int tid = threadIdx.x;
    const int w = tid >> 5, l = tid & 31;
    const int m0 = blockIdx.y * 128;
    const int n0g = blockIdx.x * 128;
    const int sec = n0g >> 9;            // 0:Q 1:K 2:V
    const int n0 = n0g & 511;

    const __half* Wsec = Wh + (long)sec * 512 * 512;
    const __half* srcs[3] = {Xh, Xl, Wsec};
    const int rbs[3] = {m0, m0, n0};

    const int NC = 512 / 32;             // 16

    auto load_stage = [&](int c) {
        const uint32_t stg = sbase + (c % 3) * PSTG;
        #pragma unroll
        for (int i = 0; i < 6; i++) {
            int id = tid + i * 256;
            int t = id >> 9, rem = id & 511, row = rem >> 2, ch = rem & 3;
            const __half* g = srcs[t] + (long)(rbs[t] + row) * 512 + (long)c * 32 + ch * 8;
            uint32_t sa = stg + t * PTILE + row * 64 + ((ch ^ ((row >> 1) & 3)) << 4);
            cp16(sa, g);
        }
        asm volatile("cp.async.commit_group;" ::: "memory");
    };

    float acc[4][4][4] = {};
    const int wm = (w & 1) * 64;
    const int wn = (w >> 1) * 32;
    const int matI = l >> 3, rim = l & 7;

    load_stage(0);
    load_stage(1);

    for (int c = 0; c < NC; c++) {
        asm volatile("cp.async.wait_group 1;" ::: "memory");
        __syncthreads();
        if (c + 2 < NC) load_stage(c + 2);
        else asm volatile("cp.async.commit_group;" ::: "memory");

        const uint32_t stg = sbase + (c % 3) * PSTG;
        #pragma unroll
        for (int kk = 0; kk < 2; kk++) {
            uint32_t fB[2][4];
            #pragma unroll
            for (int p = 0; p < 2; p++) {
                int n = wn + p * 16 + (matI >> 1) * 8 + rim;
                int ch = kk * 2 + (matI & 1);
                ldsm_x4(fB[p], stg + 2 * PTILE + n * 64 + ((ch ^ ((n >> 1) & 3)) << 4));
            }
            #pragma unroll
            for (int mi = 0; mi < 4; mi++) {
                int row = wm + mi * 16 + rim + (matI & 1) * 8;
                int ch = kk * 2 + (matI >> 1);
                uint32_t off = row * 64 + ((ch ^ ((row >> 1) & 3)) << 4);
                uint32_t fAh[4], fAl[4];
                ldsm_x4(fAh, stg + off);
                ldsm_x4(fAl, stg + PTILE + off);
                #pragma unroll
                for (int ni = 0; ni < 4; ni++) {
                    const uint32_t* b = &fB[ni >> 1][(ni & 1) * 2];
                    hmma(acc[mi][ni], fAh, b);
                    hmma(acc[mi][ni], fAl, b);
                }
            }
        }
    }
    asm volatile("cp.async.wait_group 0;" ::: "memory");
    __syncthreads();

    // epilogue: regs (+bias) -> SMEM -> coalesced fp16 GMEM
    const float* bias = (sec == 0) ? bq : (sec == 1) ? bk : bv;
    float* sf = reinterpret_cast<float*>(smem_al);   // [128][129]
    const int r_ = l >> 2, cq = (l & 3) * 2;
    const bool tr = (sec == 2);

    #pragma unroll
    for (int mi = 0; mi < 4; mi++)
        #pragma unroll
        for (int ni = 0; ni < 4; ni++) {
            int m = wm + mi * 16 + r_;
            int n = wn + ni * 8 + cq;
            float b0 = bias[n0 + n], b1 = bias[n0 + n + 1];
            float v00 = acc[mi][ni][0] + b0, v01 = acc[mi][ni][1] + b1;
            float v10 = acc[mi][ni][2] + b0, v11 = acc[mi][ni][3] + b1;
            if (tr) {
                sf[n * 129 + m] = v00;       sf[(n + 1) * 129 + m] = v01;
                sf[n * 129 + m + 8] = v10;   sf[(n + 1) * 129 + m + 8] = v11;
            } else {
                sf[m * 129 + n] = v00;       sf[m * 129 + n + 1] = v01;
                sf[(m + 8) * 129 + n] = v10; sf[(m + 8) * 129 + n + 1] = v11;
            }
        }
    __syncthreads();

    __half* Cd = (sec == 0) ? Qh : (sec == 1) ? Kh : Vth;
    #pragma unroll
    for (int i = 0; i < 16; i++) {
        int idx = (tid + i * 256) << 2;
        int row = idx >> 7, col = idx & 127;
        const float* p = &sf[row * 129 + col];
        uint32_t hp[2];
        #pragma unroll
        for (int q = 0; q < 2; q++) {
            __half2 H = __halves2half2(__float2half_rn(p[2 * q]), __float2half_rn(p[2 * q + 1]));
            hp[q] = *reinterpret_cast<uint32_t*>(&H);
        }
        long dst = tr ? ((long)(n0 + row) * 8192 + m0 + col)
                      : ((long)(m0 + row) * 512 + n0 + col);
        *reinterpret_cast<uint2*>(Cd + dst) = make_uint2(hp[0], hp[1]);
    }
}

// =============================================================================
// big GEMM: 128x128 tile, 256 thr, warp 64x32, 1-term, f32 out, 3-stage, 2 CTA/SM
// C[m,n] = alpha * sum_k A[m,k] * B[n,k]
// =============================================================================
#define GSTG  16384                      // A 8KB + B 8KB per stage
#define SMEM_G (128 * 129 * 4 + 256)     // 66304 >= 3*GSTG (49152)

__global__ void __launch_bounds__(256, 2)
big_gemm(const __half* __restrict__ A, const __half* __restrict__ B,
         float* __restrict__ Cf,
         int K, int lda, int ldb, int ldc,
         long sA, long sB, long sC, float alpha)
{
    extern __shared__ char smem_raw[];
    const uint32_t raw32 = smem_u32(smem_raw);
    const uint32_t sbase = (raw32 + 127) & ~127u;
    char* smem_al = smem_raw + (sbase - raw32);

    const int tid = threadIdx.x;
    const int w = tid >> 5, l = tid & 31;
    const int m0 = blockIdx.y * 128;
    const int n0 = blockIdx.x * 128;
    const int z = blockIdx.z;

    const __half* Ab = A + z * sA;
    const __half* Bb = B + z * sB;

    const int NC = K / 32;

    auto load_stage = [&](int c) {
        const uint32_t stg = sbase + (c % 3) * GSTG;
        #pragma unroll
        for (int i = 0; i < 4; i++) {
            int id = tid + i * 256;
            int t = id >> 9, rem = id & 511, row = rem >> 2, ch = rem & 3;
            const __half* g = (t == 0)
                ? Ab + (long)(m0 + row) * lda + (long)c * 32 + ch * 8
                : Bb + (long)(n0 + row) * ldb + (long)c * 32 + ch * 8;
            uint32_t sa = stg + t * 8192 + row * 64 + ((ch ^ ((row >> 1) & 3)) << 4);
            cp16(sa, g);
        }
        asm volatile("cp.async.commit_group;" ::: "memory");
    };

    float acc[4][4][4] = {};
    const int wm = (w & 1) * 64;
    const int wn = (w >> 1) * 32;
    const int matI = l >> 3, rim = l & 7;

    load_stage(0);
    load_stage(1);

    for (int c = 0; c < NC; c++) {
        asm volatile("cp.async.wait_group 1;" ::: "memory");
        __syncthreads();
        if (c + 2 < NC) load_stage(c + 2);
        else asm volatile("cp.async.commit_group;" ::: "memory");

        const uint32_t stg = sbase + (c % 3) * GSTG;
        const uint32_t bbase = stg + 8192;
        #pragma unroll
        for (int kk = 0; kk < 2; kk++) {
            uint32_t fB[2][4];
            #pragma unroll
            for (int p = 0; p < 2; p++) {
                int n = wn + p * 16 + (matI >> 1) * 8 + rim;
                int ch = kk * 2 + (matI & 1);
                ldsm_x4(fB[p], bbase + n * 64 + ((ch ^ ((n >> 1) & 3)) << 4));
            }
            #pragma unroll
            for (int mi = 0; mi < 4; mi++) {
                int row = wm + mi * 16 + rim + (matI & 1) * 8;
                int ch = kk * 2 + (matI >> 1);
                uint32_t fA[4];
                ldsm_x4(fA, stg + row * 64 + ((ch ^ ((row >> 1) & 3)) << 4));
                #pragma unroll
                for (int ni = 0; ni < 4; ni++)
                    hmma(acc[mi][ni], fA, &fB[ni >> 1][(ni & 1) * 2]);
            }
        }
    }
    asm volatile("cp.async.wait_group 0;" ::: "memory");
    __syncthreads();

    // epilogue: regs -> SMEM [128][129] -> coalesced f32 GMEM
    float* sf = reinterpret_cast<float*>(smem_al);
    const int r_ = l >> 2, cq = (l & 3) * 2;

    #pragma unroll
    for (int mi = 0; mi < 4; mi++)
        #pragma unroll
        for (int ni = 0; ni < 4; ni++) {
            int m = wm + mi * 16 + r_;
            int n = wn + ni * 8 + cq;
            sf[m * 129 + n] = acc[mi][ni][0] * alpha;
            sf[m * 129 + n + 1] = acc[mi][ni][1] * alpha;
            sf[(m + 8) * 129 + n] = acc[mi][ni][2] * alpha;
            sf[(m + 8) * 129 + n + 1] = acc[mi][ni][3] * alpha;
        }
    __syncthreads();

    float* Cb = Cf + z * sC;
    #pragma unroll
    for (int i = 0; i < 16; i++) {
        int idx = (tid + i * 256) << 2;
        int row = idx >> 7, col = idx & 127;
        const float* p = &sf[row * 129 + col];
        float4 v = make_float4(p[0], p[1], p[2], p[3]);
        *reinterpret_cast<float4*>(Cb + (long)(m0 + row) * ldc + n0 + col) = v;
    }
}

// ======================= conversions =======================
// X -> hi/lo fp16, vectorized (NX/4 threads of float4)
__global__ void cvtX_kernel(const float* __restrict__ in, __half* __restrict__ h,
                            __half* __restrict__ l, int n4)
{
    int i = blockIdx.x * blockDim.x + threadIdx.x;
    if (i < n4) {
        float4 v = reinterpret_cast<const float4*>(in)[i];
        __half2 h0 = __floats2half2_rn(v.x, v.y), h1 = __floats2half2_rn(v.z, v.w);
        float2 hf0 = __half22float2(h0), hf1 = __half22float2(h1);
        __half2 l0 = __floats2half2_rn(v.x - hf0.x, v.y - hf0.y);
        __half2 l1 = __floats2half2_rn(v.z - hf1.x, v.w - hf1.y);
        reinterpret_cast<uint2*>(h)[i] = make_uint2(*(uint32_t*)&h0, *(uint32_t*)&h1);
        reinterpret_cast<uint2*>(l)[i] = make_uint2(*(uint32_t*)&l0, *(uint32_t*)&l1);
    }
}
// W (3 matrices) -> fp16, one launch
__global__ void cvtW_kernel(const float* __restrict__ Wq, const float* __restrict__ Wk,
                            const float* __restrict__ Wv, __half* __restrict__ h, int NW4)
{
    int i = blockIdx.x * blockDim.x + threadIdx.x;
    if (i < 3 * NW4) {
        const float* src = (i < NW4) ? Wq : (i < 2 * NW4) ? Wk : Wv;
        int j = (i < NW4) ? i : (i < 2 * NW4) ? i - NW4 : i - 2 * NW4;
        float4 v = reinterpret_cast<const float4*>(src)[j];
        __half2 h0 = __floats2half2_rn(v.x, v.y), h1 = __floats2half2_rn(v.z, v.w);
        reinterpret_cast<uint2*>(h)[i] = make_uint2(*(uint32_t*)&h0, *(uint32_t*)&h1);
    }
}

// ======================= softmax (f32 in place + fp16 out), float4 =======================
__global__ void __launch_bounds__(256) softmax_kernel(
    float* __restrict__ att, __half* __restrict__ Ph)
{
    const int S = 2048;
    const long rowoff = (long)blockIdx.x * S;
    float4* row4 = reinterpret_cast<float4*>(att + rowoff);
    const int t = threadIdx.x, lane = t & 31, warp = t >> 5;

    __shared__ float red_max[8], red_sum[8];

    float4 v[2];
    float vmax = -1e30f;
    #pragma unroll
    for (int i = 0; i < 2; i++) {
        v[i] = row4[t + i * 256];
        vmax = fmaxf(vmax, fmaxf(fmaxf(v[i].x, v[i].y), fmaxf(v[i].z, v[i].w)));
    }
    #pragma unroll
    for (int o = 16; o > 0; o >>= 1) vmax = fmaxf(vmax, __shfl_xor_sync(~0u, vmax, o));
    if (lane == 0) red_max[warp] = vmax;
    __syncthreads();
    vmax = red_max[0];
    #pragma unroll
    for (int i = 1; i < 8; i++) vmax = fmaxf(vmax, red_max[i]);

    float sum = 0.f;
    #pragma unroll
    for (int i = 0; i < 2; i++) {
        v[i].x = __expf(v[i].x - vmax); v[i].y = __expf(v[i].y - vmax);
        v[i].z = __expf(v[i].z - vmax); v[i].w = __expf(v[i].w - vmax);
        sum += (v[i].x + v[i].y) + (v[i].z + v[i].w);
    }
    #pragma unroll
    for (int o = 16; o > 0; o >>= 1) sum += __shfl_xor_sync(~0u, sum, o);
    if (lane == 0) red_sum[warp] = sum;
    __syncthreads();
    float tot = red_sum[0];
    #pragma unroll
    for (int i = 1; i < 8; i++) tot += red_sum[i];
    float inv = 1.0f / tot;

    uint2* Ph2 = reinterpret_cast<uint2*>(Ph + rowoff);
    #pragma unroll
    for (int i = 0; i < 2; i++) {
        float4 p;
        p.x = v[i].x * inv; p.y = v[i].y * inv;
        p.z = v[i].z * inv; p.w = v[i].w * inv;
        row4[t + i * 256] = p;
        __half2 a = __floats2half2_rn(p.x, p.y), b = __floats2half2_rn(p.z, p.w);
        Ph2[t + i * 256] = make_uint2(*(uint32_t*)&a, *(uint32_t*)&b);
    }
}

// ======================= launch =======================
extern "C" void kernel_launch(void* const* d_in, const int* in_sizes, int n_in,
                              void* d_out, int out_size)
{
    const float* x  = (const float*)d_in[0];
    const float* Wq = (const float*)d_in[1];
    const float* bq = (const float*)d_in[2];
    const float* Wk = (const float*)d_in[3];
    const float* bk = (const float*)d_in[4];
    const float* Wv = (const float*)d_in[5];
    const float* bv = (const float*)d_in[6];

    const int B = 4, S = 2048, D = 512;
    float* att = (float*)d_out;
    float* wtd = att + (size_t)B * S * S;

    __half *Xh, *Xl, *Wh, *Qh, *Kh, *Vth, *Ph;
    cudaGetSymbolAddress((void**)&Xh, g_Xh);   cudaGetSymbolAddress((void**)&Xl, g_Xl);
    cudaGetSymbolAddress((void**)&Wh, g_Wh);
    cudaGetSymbolAddress((void**)&Qh, g_Qh);
    cudaGetSymbolAddress((void**)&Kh, g_Kh);
    cudaGetSymbolAddress((void**)&Vth, g_Vth);
    cudaGetSymbolAddress((void**)&Ph, g_Ph);

    cudaFuncSetAttribute(qkv_gemm, cudaFuncAttributeMaxDynamicSharedMemorySize, SMEM_P);
    cudaFuncSetAttribute(big_gemm, cudaFuncAttributeMaxDynamicSharedMemorySize, SMEM_G);

    const int NX4 = B * S * D / 4;       // 1048576
    const int NW4 = D * D / 4;           // 65536
    cvtX_kernel<<<(NX4 + 255) / 256, 256>>>(x, Xh, Xl, NX4);
    cvtW_kernel<<<(3 * NW4 + 255) / 256, 256>>>(Wq, Wk, Wv, Wh, NW4);

    dim3 blk(256);

    // fused QKV projections (2-term), V transposed
    dim3 gqkv(12, 64, 1);
    qkv_gemm<<<gqkv, blk, SMEM_P>>>(Xh, Xl, Wh, bq, bk, bv, Qh, Kh, Vth);

    // scores: att[b] = Q[b] @ K[b]^T * scale
    const float scale = 1.0f / sqrtf((float)D);
    dim3 gsc(S / 128, S / 128, B);
    big_gemm<<<gsc, blk, SMEM_G>>>(Qh, Kh, att, D, D, D, S,
                                   (long)S * D, (long)S * D, (long)S * S, scale);

    // softmax
    softmax_kernel<<<B * S, 256>>>(att, Ph);

    // weighted: wtd[b] = P[b] @ V[b]  (Vt is [512, 8192], per-batch col offset b*2048)
    dim3 gw(D / 128, S / 128, B);
    big_gemm<<<gw, blk, SMEM_G>>>(Ph, Vth, wtd, S, S, 8192, D,
                                  (long)S * S, (long)S, (long)S * D, 1.0f);
}

// round 8
// speedup vs baseline: 6.2218x; 1.0606x over previous
#include <cuda_runtime.h>
#include <cuda_fp16.h>
#include <math.h>
#include <stdint.h>

// ======================= scratch (static, allocation-free) =======================
static __device__ __half g_Xh[8192UL * 512], g_Xl[8192UL * 512];
static __device__ __half g_Wh[3UL * 512 * 512];
static __device__ __half g_Qh[8192UL * 512];
static __device__ __half g_Kh[8192UL * 512];
static __device__ __half g_Vth[512UL * 8192];
static __device__ __half g_Ph[4UL * 2048 * 2048];

// ======================= helpers (base ISA: sm_80/75 features only) =======================
__device__ __forceinline__ uint32_t smem_u32(const void* p) {
    uint32_t a;
    asm("{ .reg .u64 t; cvta.to.shared.u64 t, %1; cvt.u32.u64 %0, t; }" : "=r"(a) : "l"(p));
    return a;
}
__device__ __forceinline__ void ldsm_x4(uint32_t r[4], uint32_t addr) {
    asm volatile("ldmatrix.sync.aligned.m8n8.x4.shared.b16 {%0,%1,%2,%3}, [%4];"
                 : "=r"(r[0]), "=r"(r[1]), "=r"(r[2]), "=r"(r[3]) : "r"(addr));
}
__device__ __forceinline__ void hmma(float* c, const uint32_t* a, const uint32_t* b) {
    asm volatile(
        "mma.sync.aligned.m16n8k16.row.col.f32.f16.f16.f32 "
        "{%0,%1,%2,%3}, {%4,%5,%6,%7}, {%8,%9}, {%0,%1,%2,%3};"
        : "+f"(c[0]), "+f"(c[1]), "+f"(c[2]), "+f"(c[3])
        : "r"(a[0]), "r"(a[1]), "r"(a[2]), "r"(a[3]), "r"(b[0]), "r"(b[1]));
}
__device__ __forceinline__ void cp16(uint32_t s, const void* g) {
    asm volatile("cp.async.cg.shared.global [%0], [%1], 16;" :: "r"(s), "l"(g) : "memory");
}

// =============================================================================
// fused QKV projection: C_sec = X @ Wsec^T + bsec, 2-term (Xh+Xl)
// grid.x = 12 (section = n0g>>9), grid.y = 64
// sec 0 -> Qh [8192,512], sec 1 -> Kh [8192,512], sec 2 -> Vth [512,8192] transposed
// =============================================================================
#define PTILE 8192                       // 128x32 fp16 tile
#define PSTG  (3 * PTILE)                // Xh, Xl, W tiles
#define SMEM_P (3 * PSTG + 256)

__global__ void __launch_bounds__(256, 2)
qkv_gemm(const __half* __restrict__ Xh, const __half* __restrict__ Xl,
         const __half* __restrict__ Wh,
         const float* __restrict__ bq, const float* __restrict__ bk,
         const float* __restrict__ bv,
         __half* __restrict__ Qh, __half* __restrict__ Kh, __half* __restrict__ Vth)
{
    extern __shared__ char smem_raw[];
    const uint32_t raw32 = smem_u32(smem_raw);
    const uint32_t sbase = (raw32 + 127) & ~127u;
    char* smem_al = smem_raw + (sbase - raw32);

    const int tid = threadIdx.x;
    const int w = tid >> 5, l = tid & 31;
    const int m0 = blockIdx.y * 128;
    const int n0g = blockIdx.x * 128;
    const int sec = n0g >> 9;            // 0:Q 1:K 2:V
    const int n0 = n0g & 511;

    const __half* Wsec = Wh + (long)sec * 512 * 512;
    const __half* srcs[3] = {Xh, Xl, Wsec};
    const int rbs[3] = {m0, m0, n0};

    const int NC = 512 / 32;             // 16

    auto load_stage = [&](int c) {
        const uint32_t stg = sbase + (c % 3) * PSTG;
        #pragma unroll
        for (int i = 0; i < 6; i++) {
            int id = tid + i * 256;
            int t = id >> 9, rem = id & 511, row = rem >> 2, ch = rem & 3;
            const __half* g = srcs[t] + (long)(rbs[t] + row) * 512 + (long)c * 32 + ch * 8;
            uint32_t sa = stg + t * PTILE + row * 64 + ((ch ^ ((row >> 1) & 3)) << 4);
            cp16(sa, g);
        }
        asm volatile("cp.async.commit_group;" ::: "memory");
    };

    float acc[4][4][4] = {};
    const int wm = (w & 1) * 64;
    const int wn = (w >> 1) * 32;
    const int matI = l >> 3, rim = l & 7;

    load_stage(0);
    load_stage(1);

    for (int c = 0; c < NC; c++) {
        asm volatile("cp.async.wait_group 1;" ::: "memory");
        __syncthreads();
        if (c + 2 < NC) load_stage(c + 2);
        else asm volatile("cp.async.commit_group;" ::: "memory");

        const uint32_t stg = sbase + (c % 3) * PSTG;
        #pragma unroll
        for (int kk = 0; kk < 2; kk++) {
            uint32_t fB[2][4];
            #pragma unroll
            for (int p = 0; p < 2; p++) {
                int n = wn + p * 16 + (matI >> 1) * 8 + rim;
                int ch = kk * 2 + (matI & 1);
                ldsm_x4(fB[p], stg + 2 * PTILE + n * 64 + ((ch ^ ((n >> 1) & 3)) << 4));
            }
            #pragma unroll
            for (int mi = 0; mi < 4; mi++) {
                int row = wm + mi * 16 + rim + (matI & 1) * 8;
                int ch = kk * 2 + (matI >> 1);
                uint32_t off = row * 64 + ((ch ^ ((row >> 1) & 3)) << 4);
                uint32_t fAh[4], fAl[4];
                ldsm_x4(fAh, stg + off);
                ldsm_x4(fAl, stg + PTILE + off);
                #pragma unroll
                for (int ni = 0; ni < 4; ni++) {
                    const uint32_t* b = &fB[ni >> 1][(ni & 1) * 2];
                    hmma(acc[mi][ni], fAh, b);
                    hmma(acc[mi][ni], fAl, b);
                }
            }
        }
    }
    asm volatile("cp.async.wait_group 0;" ::: "memory");
    __syncthreads();

    // epilogue: regs (+bias) -> SMEM -> coalesced fp16 GMEM
    const float* bias = (sec == 0) ? bq : (sec == 1) ? bk : bv;
    float* sf = reinterpret_cast<float*>(smem_al);   // [128][129]
    const int r_ = l >> 2, cq = (l & 3) * 2;
    const bool tr = (sec == 2);

    #pragma unroll
    for (int mi = 0; mi < 4; mi++)
        #pragma unroll
        for (int ni = 0; ni < 4; ni++) {
            int m = wm + mi * 16 + r_;
            int n = wn + ni * 8 + cq;
            float b0 = bias[n0 + n], b1 = bias[n0 + n + 1];
            float v00 = acc[mi][ni][0] + b0, v01 = acc[mi][ni][1] + b1;
            float v10 = acc[mi][ni][2] + b0, v11 = acc[mi][ni][3] + b1;
            if (tr) {
                sf[n * 129 + m] = v00;       sf[(n + 1) * 129 + m] = v01;
                sf[n * 129 + m + 8] = v10;   sf[(n + 1) * 129 + m + 8] = v11;
            } else {
                sf[m * 129 + n] = v00;       sf[m * 129 + n + 1] = v01;
                sf[(m + 8) * 129 + n] = v10; sf[(m + 8) * 129 + n + 1] = v11;
            }
        }
    __syncthreads();

    __half* Cd = (sec == 0) ? Qh : (sec == 1) ? Kh : Vth;
    #pragma unroll
    for (int i = 0; i < 16; i++) {
        int idx = (tid + i * 256) << 2;
        int row = idx >> 7, col = idx & 127;
        const float* p = &sf[row * 129 + col];
        uint32_t hp[2];
        #pragma unroll
        for (int q = 0; q < 2; q++) {
            __half2 H = __halves2half2(__float2half_rn(p[2 * q]), __float2half_rn(p[2 * q + 1]));
            hp[q] = *reinterpret_cast<uint32_t*>(&H);
        }
        long dst = tr ? ((long)(n0 + row) * 8192 + m0 + col)
                      : ((long)(m0 + row) * 512 + n0 + col);
        *reinterpret_cast<uint2*>(Cd + dst) = make_uint2(hp[0], hp[1]);
    }
}

// =============================================================================
// big GEMM: 128 threads, tile 128x128, warp 64x64, 1-term, f32 out,
// 3-stage pipeline, 2 CTA/SM.  C[m,n] = alpha * sum_k A[m,k]*B[n,k]
// =============================================================================
#define GSTG  16384                      // A 8KB + B 8KB per stage
#define SMEM_G (128 * 129 * 4 + 256)     // 66304 >= 3*GSTG (49152)

__global__ void __launch_bounds__(128, 2)
big_gemm(const __half* __restrict__ A, const __half* __restrict__ B,
         float* __restrict__ Cf,
         int K, int lda, int ldb, int ldc,
         long sA, long sB, long sC, float alpha)
{
    extern __shared__ char smem_raw[];
    const uint32_t raw32 = smem_u32(smem_raw);
    const uint32_t sbase = (raw32 + 127) & ~127u;
    char* smem_al = smem_raw + (sbase - raw32);

    const int tid = threadIdx.x;
    const int w = tid >> 5, l = tid & 31;
    const int m0 = blockIdx.y * 128;
    const int n0 = blockIdx.x * 128;
    const int z = blockIdx.z;

    const __half* Ab = A + z * sA;
    const __half* Bb = B + z * sB;

    const int NC = K / 32;

    auto load_stage = [&](int c) {
        const uint32_t stg = sbase + (c % 3) * GSTG;
        #pragma unroll
        for (int i = 0; i < 8; i++) {
            int id = tid + i * 128;
            int t = id >> 9, rem = id & 511, row = rem >> 2, ch = rem & 3;
            const __half* g = (t == 0)
                ? Ab + (long)(m0 + row) * lda + (long)c * 32 + ch * 8
                : Bb + (long)(n0 + row) * ldb + (long)c * 32 + ch * 8;
            uint32_t sa = stg + t * 8192 + row * 64 + ((ch ^ ((row >> 1) & 3)) << 4);
            cp16(sa, g);
        }
        asm volatile("cp.async.commit_group;" ::: "memory");
    };

    float acc[4][8][4] = {};
    const int wm = (w & 1) * 64;     // 2x2 warp grid
    const int wn = (w >> 1) * 64;
    const int matI = l >> 3, rim = l & 7;

    load_stage(0);
    load_stage(1);

    for (int c = 0; c < NC; c++) {
        asm volatile("cp.async.wait_group 1;" ::: "memory");
        __syncthreads();
        if (c + 2 < NC) load_stage(c + 2);
        else asm volatile("cp.async.commit_group;" ::: "memory");

        const uint32_t stg = sbase + (c % 3) * GSTG;
        const uint32_t bbase = stg + 8192;
        #pragma unroll
        for (int kk = 0; kk < 2; kk++) {
            uint32_t fB[4][4];
            #pragma unroll
            for (int p = 0; p < 4; p++) {
                int n = wn + p * 16 + (matI >> 1) * 8 + rim;
                int ch = kk * 2 + (matI & 1);
                ldsm_x4(fB[p], bbase + n * 64 + ((ch ^ ((n >> 1) & 3)) << 4));
            }
            #pragma unroll
            for (int mi = 0; mi < 4; mi++) {
                int row = wm + mi * 16 + rim + (matI & 1) * 8;
                int ch = kk * 2 + (matI >> 1);
                uint32_t fA[4];
                ldsm_x4(fA, stg + row * 64 + ((ch ^ ((row >> 1) & 3)) << 4));
                #pragma unroll
                for (int ni = 0; ni < 8; ni++)
                    hmma(acc[mi][ni], fA, &fB[ni >> 1][(ni & 1) * 2]);
            }
        }
    }
    asm volatile("cp.async.wait_group 0;" ::: "memory");
    __syncthreads();

    // epilogue: regs -> SMEM [128][129] -> coalesced f32 GMEM
    float* sf = reinterpret_cast<float*>(smem_al);
    const int r_ = l >> 2, cq = (l & 3) * 2;

    #pragma unroll
    for (int mi = 0; mi < 4; mi++)
        #pragma unroll
        for (int ni = 0; ni < 8; ni++) {
            int m = wm + mi * 16 + r_;
            int n = wn + ni * 8 + cq;
            sf[m * 129 + n] = acc[mi][ni][0] * alpha;
            sf[m * 129 + n + 1] = acc[mi][ni][1] * alpha;
            sf[(m + 8) * 129 + n] = acc[mi][ni][2] * alpha;
            sf[(m + 8) * 129 + n + 1] = acc[mi][ni][3] * alpha;
        }
    __syncthreads();

    float* Cb = Cf + z * sC;
    #pragma unroll
    for (int i = 0; i < 32; i++) {
        int idx = (tid + i * 128) << 2;
        int row = idx >> 7, col = idx & 127;
        const float* p = &sf[row * 129 + col];
        float4 v = make_float4(p[0], p[1], p[2], p[3]);
        *reinterpret_cast<float4*>(Cb + (long)(m0 + row) * ldc + n0 + col) = v;
    }
}

// ======================= conversions =======================
__global__ void cvtX_kernel(const float* __restrict__ in, __half* __restrict__ h,
                            __half* __restrict__ l, int n4)
{
    int i = blockIdx.x * blockDim.x + threadIdx.x;
    if (i < n4) {
        float4 v = reinterpret_cast<const float4*>(in)[i];
        __half2 h0 = __floats2half2_rn(v.x, v.y), h1 = __floats2half2_rn(v.z, v.w);
        float2 hf0 = __half22float2(h0), hf1 = __half22float2(h1);
        __half2 l0 = __floats2half2_rn(v.x - hf0.x, v.y - hf0.y);
        __half2 l1 = __floats2half2_rn(v.z - hf1.x, v.w - hf1.y);
        reinterpret_cast<uint2*>(h)[i] = make_uint2(*(uint32_t*)&h0, *(uint32_t*)&h1);
        reinterpret_cast<uint2*>(l)[i] = make_uint2(*(uint32_t*)&l0, *(uint32_t*)&l1);
    }
}
__global__ void cvtW_kernel(const float* __restrict__ Wq, const float* __restrict__ Wk,
                            const float* __restrict__ Wv, __half* __restrict__ h, int NW4)
{
    int i = blockIdx.x * blockDim.x + threadIdx.x;
    if (i < 3 * NW4) {
        const float* src = (i < NW4) ? Wq : (i < 2 * NW4) ? Wk : Wv;
        int j = (i < NW4) ? i : (i < 2 * NW4) ? i - NW4 : i - 2 * NW4;
        float4 v = reinterpret_cast<const float4*>(src)[j];
        __half2 h0 = __floats2half2_rn(v.x, v.y), h1 = __floats2half2_rn(v.z, v.w);
        reinterpret_cast<uint2*>(h)[i] = make_uint2(*(uint32_t*)&h0, *(uint32_t*)&h1);
    }
}

// ======================= softmax (f32 in place + fp16 out), float4 =======================
__global__ void __launch_bounds__(256) softmax_kernel(
    float* __restrict__ att, __half* __restrict__ Ph)
{
    const int S = 2048;
    const long rowoff = (long)blockIdx.x * S;
    float4* row4 = reinterpret_cast<float4*>(att + rowoff);
    const int t = threadIdx.x, lane = t & 31, warp = t >> 5;

    __shared__ float red_max[8], red_sum[8];

    float4 v[2];
    float vmax = -1e30f;
    #pragma unroll
    for (int i = 0; i < 2; i++) {
        v[i] = row4[t + i * 256];
        vmax = fmaxf(vmax, fmaxf(fmaxf(v[i].x, v[i].y), fmaxf(v[i].z, v[i].w)));
    }
    #pragma unroll
    for (int o = 16; o > 0; o >>= 1) vmax = fmaxf(vmax, __shfl_xor_sync(~0u, vmax, o));
    if (lane == 0) red_max[warp] = vmax;
    __syncthreads();
    vmax = red_max[0];
    #pragma unroll
    for (int i = 1; i < 8; i++) vmax = fmaxf(vmax, red_max[i]);

    float sum = 0.f;
    #pragma unroll
    for (int i = 0; i < 2; i++) {
        v[i].x = __expf(v[i].x - vmax); v[i].y = __expf(v[i].y - vmax);
        v[i].z = __expf(v[i].z - vmax); v[i].w = __expf(v[i].w - vmax);
        sum += (v[i].x + v[i].y) + (v[i].z + v[i].w);
    }
    #pragma unroll
    for (int o = 16; o > 0; o >>= 1) sum += __shfl_xor_sync(~0u, sum, o);
    if (lane == 0) red_sum[warp] = sum;
    __syncthreads();
    float tot = red_sum[0];
    #pragma unroll
    for (int i = 1; i < 8; i++) tot += red_sum[i];
    float inv = 1.0f / tot;

    uint2* Ph2 = reinterpret_cast<uint2*>(Ph + rowoff);
    #pragma unroll
    for (int i = 0; i < 2; i++) {
        float4 p;
        p.x = v[i].x * inv; p.y = v[i].y * inv;
        p.z = v[i].z * inv; p.w = v[i].w * inv;
        row4[t + i * 256] = p;
        __half2 a = __floats2half2_rn(p.x, p.y), b = __floats2half2_rn(p.z, p.w);
        Ph2[t + i * 256] = make_uint2(*(uint32_t*)&a, *(uint32_t*)&b);
    }
}

// ======================= launch =======================
extern "C" void kernel_launch(void* const* d_in, const int* in_sizes, int n_in,
                              void* d_out, int out_size)
{
    const float* x  = (const float*)d_in[0];
    const float* Wq = (const float*)d_in[1];
    const float* bq = (const float*)d_in[2];
    const float* Wk = (const float*)d_in[3];
    const float* bk = (const float*)d_in[4];
    const float* Wv = (const float*)d_in[5];
    const float* bv = (const float*)d_in[6];

    const int B = 4, S = 2048, D = 512;
    float* att = (float*)d_out;
    float* wtd = att + (size_t)B * S * S;

    __half *Xh, *Xl, *Wh, *Qh, *Kh, *Vth, *Ph;
    cudaGetSymbolAddress((void**)&Xh, g_Xh);   cudaGetSymbolAddress((void**)&Xl, g_Xl);
    cudaGetSymbolAddress((void**)&Wh, g_Wh);
    cudaGetSymbolAddress((void**)&Qh, g_Qh);
    cudaGetSymbolAddress((void**)&Kh, g_Kh);
    cudaGetSymbolAddress((void**)&Vth, g_Vth);
    cudaGetSymbolAddress((void**)&Ph, g_Ph);

    cudaFuncSetAttribute(qkv_gemm, cudaFuncAttributeMaxDynamicSharedMemorySize, SMEM_P);
    cudaFuncSetAttribute(big_gemm, cudaFuncAttributeMaxDynamicSharedMemorySize, SMEM_G);

    const int NX4 = B * S * D / 4;
    const int NW4 = D * D / 4;
    cvtX_kernel<<<(NX4 + 255) / 256, 256>>>(x, Xh, Xl, NX4);
    cvtW_kernel<<<(3 * NW4 + 255) / 256, 256>>>(Wq, Wk, Wv, Wh, NW4);

    // fused QKV projections (2-term), V transposed
    dim3 gqkv(12, 64, 1);
    qkv_gemm<<<gqkv, 256, SMEM_P>>>(Xh, Xl, Wh, bq, bk, bv, Qh, Kh, Vth);

    // scores: att[b] = Q[b] @ K[b]^T * scale
    const float scale = 1.0f / sqrtf((float)D);
    dim3 gsc(S / 128, S / 128, B);
    big_gemm<<<gsc, 128, SMEM_G>>>(Qh, Kh, att, D, D, D, S,
                                   (long)S * D, (long)S * D, (long)S * S, scale);

    // softmax
    softmax_kernel<<<B * S, 256>>>(att, Ph);

    // weighted: wtd[b] = P[b] @ V[b]  (Vt is [512, 8192], per-batch col offset b*2048)
    dim3 gw(D / 128, S / 128, B);
    big_gemm<<<gw, 128, SMEM_G>>>(Ph, Vth, wtd, S, S, 8192, D,
                                  (long)S * S, (long)S, (long)S * D, 1.0f);
}

// round 9
// speedup vs baseline: 6.3824x; 1.0258x over previous
#include <cuda_runtime.h>
#include <cuda_fp16.h>
#include <math.h>
#include <stdint.h>

// ======================= scratch (static, allocation-free) =======================
static __device__ __half g_Xh[8192UL * 512], g_Xl[8192UL * 512];
static __device__ __half g_Wh[3UL * 512 * 512];
static __device__ __half g_Qh[8192UL * 512];
static __device__ __half g_Kh[8192UL * 512];
static __device__ __half g_Vth[512UL * 8192];
static __device__ __half g_Ph[4UL * 2048 * 2048];

// ======================= helpers (base ISA: sm_80/75 features only) =======================
__device__ __forceinline__ uint32_t smem_u32(const void* p) {
    uint32_t a;
    asm("{ .reg .u64 t; cvta.to.shared.u64 t, %1; cvt.u32.u64 %0, t; }" : "=r"(a) : "l"(p));
    return a;
}
__device__ __forceinline__ void ldsm_x4(uint32_t r[4], uint32_t addr) {
    asm volatile("ldmatrix.sync.aligned.m8n8.x4.shared.b16 {%0,%1,%2,%3}, [%4];"
                 : "=r"(r[0]), "=r"(r[1]), "=r"(r[2]), "=r"(r[3]) : "r"(addr));
}
__device__ __forceinline__ void hmma(float* c, const uint32_t* a, const uint32_t* b) {
    asm volatile(
        "mma.sync.aligned.m16n8k16.row.col.f32.f16.f16.f32 "
        "{%0,%1,%2,%3}, {%4,%5,%6,%7}, {%8,%9}, {%0,%1,%2,%3};"
        : "+f"(c[0]), "+f"(c[1]), "+f"(c[2]), "+f"(c[3])
        : "r"(a[0]), "r"(a[1]), "r"(a[2]), "r"(a[3]), "r"(b[0]), "r"(b[1]));
}
__device__ __forceinline__ void cp16(uint32_t s, const void* g) {
    asm volatile("cp.async.cg.shared.global [%0], [%1], 16;" :: "r"(s), "l"(g) : "memory");
}

// =============================================================================
// fused QKV projection: C_sec = X @ Wsec^T + bsec, 2-term (Xh+Xl)
// grid.x = 12 (section = n0g>>9), grid.y = 64
// sec 0 -> Qh [8192,512], sec 1 -> Kh [8192,512], sec 2 -> Vth [512,8192] transposed
// =============================================================================
#define PTILE 8192                       // 128x32 fp16 tile
#define PSTG  (3 * PTILE)                // Xh, Xl, W tiles
#define SMEM_P (3 * PSTG + 256)

__global__ void __launch_bounds__(256, 2)
qkv_gemm(const __half* __restrict__ Xh, const __half* __restrict__ Xl,
         const __half* __restrict__ Wh,
         const float* __restrict__ bq, const float* __restrict__ bk,
         const float* __restrict__ bv,
         __half* __restrict__ Qh, __half* __restrict__ Kh, __half* __restrict__ Vth)
{
    extern __shared__ char smem_raw[];
    const uint32_t raw32 = smem_u32(smem_raw);
    const uint32_t sbase = (raw32 + 127) & ~127u;
    char* smem_al = smem_raw + (sbase - raw32);

    const int tid = threadIdx.x;
    const int w = tid >> 5, l = tid & 31;
    const int m0 = blockIdx.y * 128;
    const int n0g = blockIdx.x * 128;
    const int sec = n0g >> 9;            // 0:Q 1:K 2:V
    const int n0 = n0g & 511;

    const __half* Wsec = Wh + (long)sec * 512 * 512;
    const __half* srcs[3] = {Xh, Xl, Wsec};
    const int rbs[3] = {m0, m0, n0};

    const int NC = 512 / 32;             // 16

    auto load_stage = [&](int c) {
        const uint32_t stg = sbase + (c % 3) * PSTG;
        #pragma unroll
        for (int i = 0; i < 6; i++) {
            int id = tid + i * 256;
            int t = id >> 9, rem = id & 511, row = rem >> 2, ch = rem & 3;
            const __half* g = srcs[t] + (long)(rbs[t] + row) * 512 + (long)c * 32 + ch * 8;
            uint32_t sa = stg + t * PTILE + row * 64 + ((ch ^ ((row >> 1) & 3)) << 4);
            cp16(sa, g);
        }
        asm volatile("cp.async.commit_group;" ::: "memory");
    };

    float acc[4][4][4] = {};
    const int wm = (w & 1) * 64;
    const int wn = (w >> 1) * 32;
    const int matI = l >> 3, rim = l & 7;

    load_stage(0);
    load_stage(1);

    for (int c = 0; c < NC; c++) {
        asm volatile("cp.async.wait_group 1;" ::: "memory");
        __syncthreads();
        if (c + 2 < NC) load_stage(c + 2);
        else asm volatile("cp.async.commit_group;" ::: "memory");

        const uint32_t stg = sbase + (c % 3) * PSTG;
        #pragma unroll
        for (int kk = 0; kk < 2; kk++) {
            uint32_t fB[2][4];
            #pragma unroll
            for (int p = 0; p < 2; p++) {
                int n = wn + p * 16 + (matI >> 1) * 8 + rim;
                int ch = kk * 2 + (matI & 1);
                ldsm_x4(fB[p], stg + 2 * PTILE + n * 64 + ((ch ^ ((n >> 1) & 3)) << 4));
            }
            #pragma unroll
            for (int mi = 0; mi < 4; mi++) {
                int row = wm + mi * 16 + rim + (matI & 1) * 8;
                int ch = kk * 2 + (matI >> 1);
                uint32_t off = row * 64 + ((ch ^ ((row >> 1) & 3)) << 4);
                uint32_t fAh[4], fAl[4];
                ldsm_x4(fAh, stg + off);
                ldsm_x4(fAl, stg + PTILE + off);
                #pragma unroll
                for (int ni = 0; ni < 4; ni++) {
                    const uint32_t* b = &fB[ni >> 1][(ni & 1) * 2];
                    hmma(acc[mi][ni], fAh, b);
                    hmma(acc[mi][ni], fAl, b);
                }
            }
        }
    }
    asm volatile("cp.async.wait_group 0;" ::: "memory");
    __syncthreads();

    // epilogue: regs (+bias) -> SMEM -> coalesced fp16 GMEM
    const float* bias = (sec == 0) ? bq : (sec == 1) ? bk : bv;
    float* sf = reinterpret_cast<float*>(smem_al);   // [128][129]
    const int r_ = l >> 2, cq = (l & 3) * 2;
    const bool tr = (sec == 2);

    #pragma unroll
    for (int mi = 0; mi < 4; mi++)
        #pragma unroll
        for (int ni = 0; ni < 4; ni++) {
            int m = wm + mi * 16 + r_;
            int n = wn + ni * 8 + cq;
            float b0 = bias[n0 + n], b1 = bias[n0 + n + 1];
            float v00 = acc[mi][ni][0] + b0, v01 = acc[mi][ni][1] + b1;
            float v10 = acc[mi][ni][2] + b0, v11 = acc[mi][ni][3] + b1;
            if (tr) {
                sf[n * 129 + m] = v00;       sf[(n + 1) * 129 + m] = v01;
                sf[n * 129 + m + 8] = v10;   sf[(n + 1) * 129 + m + 8] = v11;
            } else {
                sf[m * 129 + n] = v00;       sf[m * 129 + n + 1] = v01;
                sf[(m + 8) * 129 + n] = v10; sf[(m + 8) * 129 + n + 1] = v11;
            }
        }
    __syncthreads();

    __half* Cd = (sec == 0) ? Qh : (sec == 1) ? Kh : Vth;
    #pragma unroll
    for (int i = 0; i < 16; i++) {
        int idx = (tid + i * 256) << 2;
        int row = idx >> 7, col = idx & 127;
        const float* p = &sf[row * 129 + col];
        uint32_t hp[2];
        #pragma unroll
        for (int q = 0; q < 2; q++) {
            __half2 H = __halves2half2(__float2half_rn(p[2 * q]), __float2half_rn(p[2 * q + 1]));
            hp[q] = *reinterpret_cast<uint32_t*>(&H);
        }
        long dst = tr ? ((long)(n0 + row) * 8192 + m0 + col)
                      : ((long)(m0 + row) * 512 + n0 + col);
        *reinterpret_cast<uint2*>(Cd + dst) = make_uint2(hp[0], hp[1]);
    }
}

// =============================================================================
// big GEMM: 128 threads, tile 128x128, warp 64x64, 1-term, f32 out,
// 3-stage cp.async pipeline + register fragment pipelining, 2 CTA/SM.
// C[m,n] = alpha * sum_k A[m,k]*B[n,k]
// =============================================================================
#define GSTG  16384                      // A 8KB + B 8KB per stage
#define SMEM_G (128 * 129 * 4 + 256)     // 66304 >= 3*GSTG (49152)

__global__ void __launch_bounds__(128, 2)
big_gemm(const __half* __restrict__ A, const __half* __restrict__ B,
         float* __restrict__ Cf,
         int K, int lda, int ldb, int ldc,
         long sA, long sB, long sC, float alpha)
{
    extern __shared__ char smem_raw[];
    const uint32_t raw32 = smem_u32(smem_raw);
    const uint32_t sbase = (raw32 + 127) & ~127u;
    char* smem_al = smem_raw + (sbase - raw32);

    const int tid = threadIdx.x;
    const int w = tid >> 5, l = tid & 31;
    const int m0 = blockIdx.y * 128;
    const int n0 = blockIdx.x * 128;
    const int z = blockIdx.z;

    const __half* Ab = A + z * sA;
    const __half* Bb = B + z * sB;

    const int NC = K / 32;

    auto load_stage = [&](int c) {
        const uint32_t stg = sbase + (c % 3) * GSTG;
        #pragma unroll
        for (int i = 0; i < 8; i++) {
            int id = tid + i * 128;
            int t = id >> 9, rem = id & 511, row = rem >> 2, ch = rem & 3;
            const __half* g = (t == 0)
                ? Ab + (long)(m0 + row) * lda + (long)c * 32 + ch * 8
                : Bb + (long)(n0 + row) * ldb + (long)c * 32 + ch * 8;
            uint32_t sa = stg + t * 8192 + row * 64 + ((ch ^ ((row >> 1) & 3)) << 4);
            cp16(sa, g);
        }
        asm volatile("cp.async.commit_group;" ::: "memory");
    };

    float acc[4][8][4] = {};
    const int wm = (w & 1) * 64;     // 2x2 warp grid
    const int wn = (w >> 1) * 64;
    const int matI = l >> 3, rim = l & 7;

    // fragment buffers: fB double-buffered by kk, fA single-step prefetch by mi
    uint32_t fB[2][4][4];
    uint32_t fA[2][4];

    auto ldB = [&](int buf, uint32_t bbase, int kk) {
        #pragma unroll
        for (int p = 0; p < 4; p++) {
            int n = wn + p * 16 + (matI >> 1) * 8 + rim;
            int ch = kk * 2 + (matI & 1);
            ldsm_x4(fB[buf][p], bbase + n * 64 + ((ch ^ ((n >> 1) & 3)) << 4));
        }
    };
    auto ldA = [&](int buf, uint32_t stg, int kk, int mi) {
        int row = wm + mi * 16 + rim + (matI & 1) * 8;
        int ch = kk * 2 + (matI >> 1);
        ldsm_x4(fA[buf], stg + row * 64 + ((ch ^ ((row >> 1) & 3)) << 4));
    };

    load_stage(0);
    load_stage(1);

    for (int c = 0; c < NC; c++) {
        asm volatile("cp.async.wait_group 1;" ::: "memory");
        __syncthreads();
        if (c + 2 < NC) load_stage(c + 2);
        else asm volatile("cp.async.commit_group;" ::: "memory");

        const uint32_t stg = sbase + (c % 3) * GSTG;
        const uint32_t bbase = stg + 8192;

        // prologue: fragments for kk=0
        ldB(0, bbase, 0);
        ldA(0, stg, 0, 0);

        #pragma unroll
        for (int kk = 0; kk < 2; kk++) {
            #pragma unroll
            for (int mi = 0; mi < 4; mi++) {
                const int cur = mi & 1;
                // prefetch next fragments while computing current
                if (mi < 3) {
                    ldA(cur ^ 1, stg, kk, mi + 1);
                } else if (kk == 0) {
                    ldB(1, bbase, 1);
                    ldA(cur ^ 1, stg, 1, 0);
                }
                #pragma unroll
                for (int ni = 0; ni < 8; ni++)
                    hmma(acc[mi][ni], fA[cur], &fB[kk][ni >> 1][(ni & 1) * 2]);
            }
        }
    }
    asm volatile("cp.async.wait_group 0;" ::: "memory");
    __syncthreads();

    // epilogue: regs -> SMEM [128][129] -> coalesced f32 GMEM
    float* sf = reinterpret_cast<float*>(smem_al);
    const int r_ = l >> 2, cq = (l & 3) * 2;

    #pragma unroll
    for (int mi = 0; mi < 4; mi++)
        #pragma unroll
        for (int ni = 0; ni < 8; ni++) {
            int m = wm + mi * 16 + r_;
            int n = wn + ni * 8 + cq;
            sf[m * 129 + n] = acc[mi][ni][0] * alpha;
            sf[m * 129 + n + 1] = acc[mi][ni][1] * alpha;
            sf[(m + 8) * 129 + n] = acc[mi][ni][2] * alpha;
            sf[(m + 8) * 129 + n + 1] = acc[mi][ni][3] * alpha;
        }
    __syncthreads();

    float* Cb = Cf + z * sC;
    #pragma unroll
    for (int i = 0; i < 32; i++) {
        int idx = (tid + i * 128) << 2;
        int row = idx >> 7, col = idx & 127;
        const float* p = &sf[row * 129 + col];
        float4 v = make_float4(p[0], p[1], p[2], p[3]);
        *reinterpret_cast<float4*>(Cb + (long)(m0 + row) * ldc + n0 + col) = v;
    }
}

// ======================= conversions =======================
__global__ void cvtX_kernel(const float* __restrict__ in, __half* __restrict__ h,
                            __half* __restrict__ l, int n4)
{
    int i = blockIdx.x * blockDim.x + threadIdx.x;
    if (i < n4) {
        float4 v = reinterpret_cast<const float4*>(in)[i];
        __half2 h0 = __floats2half2_rn(v.x, v.y), h1 = __floats2half2_rn(v.z, v.w);
        float2 hf0 = __half22float2(h0), hf1 = __half22float2(h1);
        __half2 l0 = __floats2half2_rn(v.x - hf0.x, v.y - hf0.y);
        __half2 l1 = __floats2half2_rn(v.z - hf1.x, v.w - hf1.y);
        reinterpret_cast<uint2*>(h)[i] = make_uint2(*(uint32_t*)&h0, *(uint32_t*)&h1);
        reinterpret_cast<uint2*>(l)[i] = make_uint2(*(uint32_t*)&l0, *(uint32_t*)&l1);
    }
}
__global__ void cvtW_kernel(const float* __restrict__ Wq, const float* __restrict__ Wk,
                            const float* __restrict__ Wv, __half* __restrict__ h, int NW4)
{
    int i = blockIdx.x * blockDim.x + threadIdx.x;
    if (i < 3 * NW4) {
        const float* src = (i < NW4) ? Wq : (i < 2 * NW4) ? Wk : Wv;
        int j = (i < NW4) ? i : (i < 2 * NW4) ? i - NW4 : i - 2 * NW4;
        float4 v = reinterpret_cast<const float4*>(src)[j];
        __half2 h0 = __floats2half2_rn(v.x, v.y), h1 = __floats2half2_rn(v.z, v.w);
        reinterpret_cast<uint2*>(h)[i] = make_uint2(*(uint32_t*)&h0, *(uint32_t*)&h1);
    }
}

// ======================= softmax (f32 in place + fp16 out), float4 =======================
__global__ void __launch_bounds__(256) softmax_kernel(
    float* __restrict__ att, __half* __restrict__ Ph)
{
    const int S = 2048;
    const long rowoff = (long)blockIdx.x * S;
    float4* row4 = reinterpret_cast<float4*>(att + rowoff);
    const int t = threadIdx.x, lane = t & 31, warp = t >> 5;

    __shared__ float red_max[8], red_sum[8];

    float4 v[2];
    float vmax = -1e30f;
    #pragma unroll
    for (int i = 0; i < 2; i++) {
        v[i] = row4[t + i * 256];
        vmax = fmaxf(vmax, fmaxf(fmaxf(v[i].x, v[i].y), fmaxf(v[i].z, v[i].w)));
    }
    #pragma unroll
    for (int o = 16; o > 0; o >>= 1) vmax = fmaxf(vmax, __shfl_xor_sync(~0u, vmax, o));
    if (lane == 0) red_max[warp] = vmax;
    __syncthreads();
    vmax = red_max[0];
    #pragma unroll
    for (int i = 1; i < 8; i++) vmax = fmaxf(vmax, red_max[i]);

    float sum = 0.f;
    #pragma unroll
    for (int i = 0; i < 2; i++) {
        v[i].x = __expf(v[i].x - vmax); v[i].y = __expf(v[i].y - vmax);
        v[i].z = __expf(v[i].z - vmax); v[i].w = __expf(v[i].w - vmax);
        sum += (v[i].x + v[i].y) + (v[i].z + v[i].w);
    }
    #pragma unroll
    for (int o = 16; o > 0; o >>= 1) sum += __shfl_xor_sync(~0u, sum, o);
    if (lane == 0) red_sum[warp] = sum;
    __syncthreads();
    float tot = red_sum[0];
    #pragma unroll
    for (int i = 1; i < 8; i++) tot += red_sum[i];
    float inv = 1.0f / tot;

    uint2* Ph2 = reinterpret_cast<uint2*>(Ph + rowoff);
    #pragma unroll
    for (int i = 0; i < 2; i++) {
        float4 p;
        p.x = v[i].x * inv; p.y = v[i].y * inv;
        p.z = v[i].z * inv; p.w = v[i].w * inv;
        row4[t + i * 256] = p;
        __half2 a = __floats2half2_rn(p.x, p.y), b = __floats2half2_rn(p.z, p.w);
        Ph2[t + i * 256] = make_uint2(*(uint32_t*)&a, *(uint32_t*)&b);
    }
}

// ======================= launch =======================
extern "C" void kernel_launch(void* const* d_in, const int* in_sizes, int n_in,
                              void* d_out, int out_size)
{
    const float* x  = (const float*)d_in[0];
    const float* Wq = (const float*)d_in[1];
    const float* bq = (const float*)d_in[2];
    const float* Wk = (const float*)d_in[3];
    const float* bk = (const float*)d_in[4];
    const float* Wv = (const float*)d_in[5];
    const float* bv = (const float*)d_in[6];

    const int B = 4, S = 2048, D = 512;
    float* att = (float*)d_out;
    float* wtd = att + (size_t)B * S * S;

    __half *Xh, *Xl, *Wh, *Qh, *Kh, *Vth, *Ph;
    cudaGetSymbolAddress((void**)&Xh, g_Xh);   cudaGetSymbolAddress((void**)&Xl, g_Xl);
    cudaGetSymbolAddress((void**)&Wh, g_Wh);
    cudaGetSymbolAddress((void**)&Qh, g_Qh);
    cudaGetSymbolAddress((void**)&Kh, g_Kh);
    cudaGetSymbolAddress((void**)&Vth, g_Vth);
    cudaGetSymbolAddress((void**)&Ph, g_Ph);

    cudaFuncSetAttribute(qkv_gemm, cudaFuncAttributeMaxDynamicSharedMemorySize, SMEM_P);
    cudaFuncSetAttribute(big_gemm, cudaFuncAttributeMaxDynamicSharedMemorySize, SMEM_G);

    const int NX4 = B * S * D / 4;
    const int NW4 = D * D / 4;
    cvtX_kernel<<<(NX4 + 255) / 256, 256>>>(x, Xh, Xl, NX4);
    cvtW_kernel<<<(3 * NW4 + 255) / 256, 256>>>(Wq, Wk, Wv, Wh, NW4);

    // fused QKV projections (2-term), V transposed
    dim3 gqkv(12, 64, 1);
    qkv_gemm<<<gqkv, 256, SMEM_P>>>(Xh, Xl, Wh, bq, bk, bv, Qh, Kh, Vth);

    // scores: att[b] = Q[b] @ K[b]^T * scale
    const float scale = 1.0f / sqrtf((float)D);
    dim3 gsc(S / 128, S / 128, B);
    big_gemm<<<gsc, 128, SMEM_G>>>(Qh, Kh, att, D, D, D, S,
                                   (long)S * D, (long)S * D, (long)S * S, scale);

    // softmax
    softmax_kernel<<<B * S, 256>>>(att, Ph);

    // weighted: wtd[b] = P[b] @ V[b]  (Vt is [512, 8192], per-batch col offset b*2048)
    dim3 gw(D / 128, S / 128, B);
    big_gemm<<<gw, 128, SMEM_G>>>(Ph, Vth, wtd, S, S, 8192, D,
                                  (long)S * S, (long)S, (long)S * D, 1.0f);
}

// round 10
// speedup vs baseline: 7.2790x; 1.1405x over previous
#include <cuda_runtime.h>
#include <cuda_fp16.h>
#include <math.h>
#include <stdint.h>

// ======================= scratch (static, allocation-free) =======================
static __device__ __half g_Xh[8192UL * 512];
static __device__ __half g_Wh[3UL * 512 * 512];
static __device__ __half g_Qh[8192UL * 512];
static __device__ __half g_Kh[8192UL * 512];
static __device__ __half g_Vth[512UL * 8192];
static __device__ __half g_Ph[4UL * 2048 * 2048];

// ======================= helpers (base ISA: sm_80/75 features only) =======================
__device__ __forceinline__ uint32_t smem_u32(const void* p) {
    uint32_t a;
    asm("{ .reg .u64 t; cvta.to.shared.u64 t, %1; cvt.u32.u64 %0, t; }" : "=r"(a) : "l"(p));
    return a;
}
__device__ __forceinline__ void ldsm_x4(uint32_t r[4], uint32_t addr) {
    asm volatile("ldmatrix.sync.aligned.m8n8.x4.shared.b16 {%0,%1,%2,%3}, [%4];"
                 : "=r"(r[0]), "=r"(r[1]), "=r"(r[2]), "=r"(r[3]) : "r"(addr));
}
__device__ __forceinline__ void hmma(float* c, const uint32_t* a, const uint32_t* b) {
    asm volatile(
        "mma.sync.aligned.m16n8k16.row.col.f32.f16.f16.f32 "
        "{%0,%1,%2,%3}, {%4,%5,%6,%7}, {%8,%9}, {%0,%1,%2,%3};"
        : "+f"(c[0]), "+f"(c[1]), "+f"(c[2]), "+f"(c[3])
        : "r"(a[0]), "r"(a[1]), "r"(a[2]), "r"(a[3]), "r"(b[0]), "r"(b[1]));
}
__device__ __forceinline__ void cp16(uint32_t s, const void* g) {
    asm volatile("cp.async.cg.shared.global [%0], [%1], 16;" :: "r"(s), "l"(g) : "memory");
}

// =============================================================================
// unified GEMM: 128 threads, tile 128x128, warp 64x64, 1-term fp16,
// 3-stage cp.async + register fragment pipelining, 2 CTA/SM.
// C[m,n] = alpha * sum_k A[m,k]*B[n,k] (+ bias[n] for EPI 0/1)
// EPI 0: fp16 out at [(m0+r)*ldc + n0+c] + bias          [Q/K proj]
// EPI 1: fp16 out at [(n0+r)*ldc + m0+c] + bias (transp) [V proj]
// EPI 2: f32  out at [(m0+r)*ldc + n0+c] * alpha          [scores / weighted]
// =============================================================================
#define GSTG  16384                      // A 8KB + B 8KB per stage
#define SMEM_G (128 * 129 * 4 + 256)     // 66304 >= 3*GSTG (49152)

template <int EPI>
__global__ void __launch_bounds__(128, 2)
gemm128(const __half* __restrict__ A, const __half* __restrict__ B,
        const float* __restrict__ bias,
        float* __restrict__ Cf, __half* __restrict__ Ch,
        int K, int lda, int ldb, int ldc,
        long sA, long sB, long sC, float alpha)
{
    extern __shared__ char smem_raw[];
    const uint32_t raw32 = smem_u32(smem_raw);
    const uint32_t sbase = (raw32 + 127) & ~127u;
    char* smem_al = smem_raw + (sbase - raw32);

    const int tid = threadIdx.x;
    const int w = tid >> 5, l = tid & 31;
    const int m0 = blockIdx.y * 128;
    const int n0 = blockIdx.x * 128;
    const int z = blockIdx.z;

    const __half* Ab = A + z * sA;
    const __half* Bb = B + z * sB;

    const int NC = K / 32;

    auto load_stage = [&](int c) {
        const uint32_t stg = sbase + (c % 3) * GSTG;
        #pragma unroll
        for (int i = 0; i < 8; i++) {
            int id = tid + i * 128;
            int t = id >> 9, rem = id & 511, row = rem >> 2, ch = rem & 3;
            const __half* g = (t == 0)
                ? Ab + (long)(m0 + row) * lda + (long)c * 32 + ch * 8
                : Bb + (long)(n0 + row) * ldb + (long)c * 32 + ch * 8;
            uint32_t sa = stg + t * 8192 + row * 64 + ((ch ^ ((row >> 1) & 3)) << 4);
            cp16(sa, g);
        }
        asm volatile("cp.async.commit_group;" ::: "memory");
    };

    float acc[4][8][4] = {};
    const int wm = (w & 1) * 64;     // 2x2 warp grid
    const int wn = (w >> 1) * 64;
    const int matI = l >> 3, rim = l & 7;

    // fragment buffers: fB double-buffered by kk, fA single-step prefetch by mi
    uint32_t fB[2][4][4];
    uint32_t fA[2][4];

    auto ldB = [&](int buf, uint32_t bbase, int kk) {
        #pragma unroll
        for (int p = 0; p < 4; p++) {
            int n = wn + p * 16 + (matI >> 1) * 8 + rim;
            int ch = kk * 2 + (matI & 1);
            ldsm_x4(fB[buf][p], bbase + n * 64 + ((ch ^ ((n >> 1) & 3)) << 4));
        }
    };
    auto ldA = [&](int buf, uint32_t stg, int kk, int mi) {
        int row = wm + mi * 16 + rim + (matI & 1) * 8;
        int ch = kk * 2 + (matI >> 1);
        ldsm_x4(fA[buf], stg + row * 64 + ((ch ^ ((row >> 1) & 3)) << 4));
    };

    load_stage(0);
    load_stage(1);

    for (int c = 0; c < NC; c++) {
        asm volatile("cp.async.wait_group 1;" ::: "memory");
        __syncthreads();
        if (c + 2 < NC) load_stage(c + 2);
        else asm volatile("cp.async.commit_group;" ::: "memory");

        const uint32_t stg = sbase + (c % 3) * GSTG;
        const uint32_t bbase = stg + 8192;

        ldB(0, bbase, 0);
        ldA(0, stg, 0, 0);

        #pragma unroll
        for (int kk = 0; kk < 2; kk++) {
            #pragma unroll
            for (int mi = 0; mi < 4; mi++) {
                const int cur = mi & 1;
                if (mi < 3) {
                    ldA(cur ^ 1, stg, kk, mi + 1);
                } else if (kk == 0) {
                    ldB(1, bbase, 1);
                    ldA(cur ^ 1, stg, 1, 0);
                }
                #pragma unroll
                for (int ni = 0; ni < 8; ni++)
                    hmma(acc[mi][ni], fA[cur], &fB[kk][ni >> 1][(ni & 1) * 2]);
            }
        }
    }
    asm volatile("cp.async.wait_group 0;" ::: "memory");
    __syncthreads();

    // ---------------- epilogue: regs -> SMEM [128][129] -> coalesced GMEM ----------------
    float* sf = reinterpret_cast<float*>(smem_al);
    const int r_ = l >> 2, cq = (l & 3) * 2;

    #pragma unroll
    for (int mi = 0; mi < 4; mi++)
        #pragma unroll
        for (int ni = 0; ni < 8; ni++) {
            int m = wm + mi * 16 + r_;
            int n = wn + ni * 8 + cq;
            float b0 = 0.f, b1 = 0.f;
            if (EPI != 2) { b0 = bias[n0 + n]; b1 = bias[n0 + n + 1]; }
            float v00 = acc[mi][ni][0] * alpha + b0;
            float v01 = acc[mi][ni][1] * alpha + b1;
            float v10 = acc[mi][ni][2] * alpha + b0;
            float v11 = acc[mi][ni][3] * alpha + b1;
            if (EPI == 1) {
                sf[n * 129 + m] = v00;       sf[(n + 1) * 129 + m] = v01;
                sf[n * 129 + m + 8] = v10;   sf[(n + 1) * 129 + m + 8] = v11;
            } else {
                sf[m * 129 + n] = v00;       sf[m * 129 + n + 1] = v01;
                sf[(m + 8) * 129 + n] = v10; sf[(m + 8) * 129 + n + 1] = v11;
            }
        }
    __syncthreads();

    if (EPI == 2) {
        float* Cb = Cf + z * sC;
        #pragma unroll
        for (int i = 0; i < 32; i++) {
            int idx = (tid + i * 128) << 2;
            int row = idx >> 7, col = idx & 127;
            const float* p = &sf[row * 129 + col];
            float4 v = make_float4(p[0], p[1], p[2], p[3]);
            *reinterpret_cast<float4*>(Cb + (long)(m0 + row) * ldc + n0 + col) = v;
        }
    } else {
        #pragma unroll
        for (int i = 0; i < 32; i++) {
            int idx = (tid + i * 128) << 2;
            int row = idx >> 7, col = idx & 127;
            const float* p = &sf[row * 129 + col];
            uint32_t hp[2];
            #pragma unroll
            for (int q = 0; q < 2; q++) {
                __half2 H = __halves2half2(__float2half_rn(p[2 * q]),
                                           __float2half_rn(p[2 * q + 1]));
                hp[q] = *reinterpret_cast<uint32_t*>(&H);
            }
            long dst = (EPI == 0) ? ((long)(m0 + row) * ldc + n0 + col)
                                  : ((long)(n0 + row) * ldc + m0 + col);
            *reinterpret_cast<uint2*>(Ch + dst) = make_uint2(hp[0], hp[1]);
        }
    }
}

// ======================= single fused conversion: x + Wq + Wk + Wv -> fp16 =======================
__global__ void cvt_all(const float* __restrict__ x,
                        const float* __restrict__ Wq, const float* __restrict__ Wk,
                        const float* __restrict__ Wv,
                        __half* __restrict__ Xh, __half* __restrict__ Wh,
                        int NX4, int NW4)
{
    int i = blockIdx.x * blockDim.x + threadIdx.x;
    const float* src;
    __half* dst;
    int j;
    if (i < NX4) { src = x; dst = Xh; j = i; }
    else {
        int k = i - NX4;
        if (k >= 3 * NW4) return;
        int s = k / NW4;
        j = k - s * NW4;
        src = (s == 0) ? Wq : (s == 1) ? Wk : Wv;
        dst = Wh;
        j += 0;
        // dst offset handled below via k
        float4 v = reinterpret_cast<const float4*>(src)[j];
        __half2 h0 = __floats2half2_rn(v.x, v.y), h1 = __floats2half2_rn(v.z, v.w);
        reinterpret_cast<uint2*>(Wh)[k] = make_uint2(*(uint32_t*)&h0, *(uint32_t*)&h1);
        return;
    }
    float4 v = reinterpret_cast<const float4*>(src)[j];
    __half2 h0 = __floats2half2_rn(v.x, v.y), h1 = __floats2half2_rn(v.z, v.w);
    reinterpret_cast<uint2*>(dst)[j] = make_uint2(*(uint32_t*)&h0, *(uint32_t*)&h1);
}

// ======================= softmax (f32 in place + fp16 out), float4 =======================
__global__ void __launch_bounds__(256) softmax_kernel(
    float* __restrict__ att, __half* __restrict__ Ph)
{
    const int S = 2048;
    const long rowoff = (long)blockIdx.x * S;
    float4* row4 = reinterpret_cast<float4*>(att + rowoff);
    const int t = threadIdx.x, lane = t & 31, warp = t >> 5;

    __shared__ float red_max[8], red_sum[8];

    float4 v[2];
    float vmax = -1e30f;
    #pragma unroll
    for (int i = 0; i < 2; i++) {
        v[i] = row4[t + i * 256];
        vmax = fmaxf(vmax, fmaxf(fmaxf(v[i].x, v[i].y), fmaxf(v[i].z, v[i].w)));
    }
    #pragma unroll
    for (int o = 16; o > 0; o >>= 1) vmax = fmaxf(vmax, __shfl_xor_sync(~0u, vmax, o));
    if (lane == 0) red_max[warp] = vmax;
    __syncthreads();
    vmax = red_max[0];
    #pragma unroll
    for (int i = 1; i < 8; i++) vmax = fmaxf(vmax, red_max[i]);

    float sum = 0.f;
    #pragma unroll
    for (int i = 0; i < 2; i++) {
        v[i].x = __expf(v[i].x - vmax); v[i].y = __expf(v[i].y - vmax);
        v[i].z = __expf(v[i].z - vmax); v[i].w = __expf(v[i].w - vmax);
        sum += (v[i].x + v[i].y) + (v[i].z + v[i].w);
    }
    #pragma unroll
    for (int o = 16; o > 0; o >>= 1) sum += __shfl_xor_sync(~0u, sum, o);
    if (lane == 0) red_sum[warp] = sum;
    __syncthreads();
    float tot = red_sum[0];
    #pragma unroll
    for (int i = 1; i < 8; i++) tot += red_sum[i];
    float inv = 1.0f / tot;

    uint2* Ph2 = reinterpret_cast<uint2*>(Ph + rowoff);
    #pragma unroll
    for (int i = 0; i < 2; i++) {
        float4 p;
        p.x = v[i].x * inv; p.y = v[i].y * inv;
        p.z = v[i].z * inv; p.w = v[i].w * inv;
        row4[t + i * 256] = p;
        __half2 a = __floats2half2_rn(p.x, p.y), b = __floats2half2_rn(p.z, p.w);
        Ph2[t + i * 256] = make_uint2(*(uint32_t*)&a, *(uint32_t*)&b);
    }
}

// ======================= launch =======================
extern "C" void kernel_launch(void* const* d_in, const int* in_sizes, int n_in,
                              void* d_out, int out_size)
{
    const float* x  = (const float*)d_in[0];
    const float* Wq = (const float*)d_in[1];
    const float* bq = (const float*)d_in[2];
    const float* Wk = (const float*)d_in[3];
    const float* bk = (const float*)d_in[4];
    const float* Wv = (const float*)d_in[5];
    const float* bv = (const float*)d_in[6];

    const int B = 4, S = 2048, D = 512;
    float* att = (float*)d_out;
    float* wtd = att + (size_t)B * S * S;

    __half *Xh, *Wh, *Qh, *Kh, *Vth, *Ph;
    cudaGetSymbolAddress((void**)&Xh, g_Xh);
    cudaGetSymbolAddress((void**)&Wh, g_Wh);
    cudaGetSymbolAddress((void**)&Qh, g_Qh);
    cudaGetSymbolAddress((void**)&Kh, g_Kh);
    cudaGetSymbolAddress((void**)&Vth, g_Vth);
    cudaGetSymbolAddress((void**)&Ph, g_Ph);

    cudaFuncSetAttribute(gemm128<0>, cudaFuncAttributeMaxDynamicSharedMemorySize, SMEM_G);
    cudaFuncSetAttribute(gemm128<1>, cudaFuncAttributeMaxDynamicSharedMemorySize, SMEM_G);
    cudaFuncSetAttribute(gemm128<2>, cudaFuncAttributeMaxDynamicSharedMemorySize, SMEM_G);

    const int NX4 = B * S * D / 4;       // 1048576
    const int NW4 = D * D / 4;           // 65536
    const int NALL = NX4 + 3 * NW4;
    cvt_all<<<(NALL + 255) / 256, 256>>>(x, Wq, Wk, Wv, Xh, Wh, NX4, NW4);

    // projections (1-term fp16): Q, K normal; V transposed into Vth [512, 8192]
    dim3 gproj(D / 128, (B * S) / 128, 1);
    gemm128<0><<<gproj, 128, SMEM_G>>>(Xh, Wh, bq, nullptr, Qh,
                                       D, D, D, D, 0, 0, 0, 1.0f);
    gemm128<0><<<gproj, 128, SMEM_G>>>(Xh, Wh + D * D, bk, nullptr, Kh,
                                       D, D, D, D, 0, 0, 0, 1.0f);
    gemm128<1><<<gproj, 128, SMEM_G>>>(Xh, Wh + 2 * D * D, bv, nullptr, Vth,
                                       D, D, D, 8192, 0, 0, 0, 1.0f);

    // scores: att[b] = Q[b] @ K[b]^T * scale
    const float scale = 1.0f / sqrtf((float)D);
    dim3 gsc(S / 128, S / 128, B);
    gemm128<2><<<gsc, 128, SMEM_G>>>(Qh, Kh, nullptr, att, nullptr,
                                     D, D, D, S,
                                     (long)S * D, (long)S * D, (long)S * S, scale);

    // softmax
    softmax_kernel<<<B * S, 256>>>(att, Ph);

    // weighted: wtd[b] = P[b] @ V[b]  (Vt is [512, 8192], per-batch col offset b*2048)
    dim3 gw(D / 128, S / 128, B);
    gemm128<2><<<gw, 128, SMEM_G>>>(Ph, Vth, nullptr, wtd, nullptr,
                                    S, S, 8192, D,
                                    (long)S * S, (long)S, (long)S * D, 1.0f);
}

// round 11
// speedup vs baseline: 11.8085x; 1.6223x over previous
#include <cuda_runtime.h>
#include <cuda_fp16.h>
#include <math.h>
#include <stdint.h>

// ======================= scratch (static, allocation-free) =======================
static __device__ __half g_Xh[8192UL * 512];
static __device__ __half g_Wh[3UL * 512 * 512];
static __device__ __half g_Qh[8192UL * 512];
static __device__ __half g_Kh[8192UL * 512];
static __device__ __half g_Vth[512UL * 8192];
static __device__ __half g_Ph[4UL * 2048 * 2048];

// tcgen05 path only exists in the sm_103a compilation pass
#if defined(__CUDA_ARCH__) && (defined(__CUDA_ARCH_FEAT_SM103_ALL) || \
    (defined(__CUDA_ARCH_SPECIFIC__) && (__CUDA_ARCH_SPECIFIC__ == 1030)))
#define TC_PATH 1
#else
#define TC_PATH 0
#endif

// ======================= common helpers =======================
__device__ __forceinline__ uint32_t smem_u32(const void* p) {
    uint32_t a;
    asm("{ .reg .u64 t; cvta.to.shared.u64 t, %1; cvt.u32.u64 %0, t; }" : "=r"(a) : "l"(p));
    return a;
}
__device__ __forceinline__ void ldsm_x4(uint32_t r[4], uint32_t addr) {
    asm volatile("ldmatrix.sync.aligned.m8n8.x4.shared.b16 {%0,%1,%2,%3}, [%4];"
                 : "=r"(r[0]), "=r"(r[1]), "=r"(r[2]), "=r"(r[3]) : "r"(addr));
}
__device__ __forceinline__ void hmma(float* c, const uint32_t* a, const uint32_t* b) {
    asm volatile(
        "mma.sync.aligned.m16n8k16.row.col.f32.f16.f16.f32 "
        "{%0,%1,%2,%3}, {%4,%5,%6,%7}, {%8,%9}, {%0,%1,%2,%3};"
        : "+f"(c[0]), "+f"(c[1]), "+f"(c[2]), "+f"(c[3])
        : "r"(a[0]), "r"(a[1]), "r"(a[2]), "r"(a[3]), "r"(b[0]), "r"(b[1]));
}
__device__ __forceinline__ void cp16(uint32_t s, const void* g) {
    asm volatile("cp.async.cg.shared.global [%0], [%1], 16;" :: "r"(s), "l"(g) : "memory");
}

#if TC_PATH
__device__ __forceinline__ uint32_t elect_one() {
    uint32_t pred;
    asm volatile("{ .reg .pred p; elect.sync _|p, 0xFFFFFFFF; selp.b32 %0, 1, 0, p; }" : "=r"(pred));
    return pred;
}
#define MBAR_INIT(a, n) asm volatile("mbarrier.init.shared.b64 [%0], %1;" :: "r"(a), "r"(n) : "memory")
#define MBAR_INVAL(a)   asm volatile("mbarrier.inval.shared.b64 [%0];" :: "r"(a) : "memory")
#define MBAR_WAIT(addr, par) do {                                               \
    uint32_t _m = (addr), _p = (par), _d;                                       \
    asm volatile("{ .reg .pred p;"                                              \
        " mbarrier.try_wait.parity.acquire.cta.shared::cta.b64 p, [%1], %2;"    \
        " selp.b32 %0, 1, 0, p; }" : "=r"(_d) : "r"(_m), "r"(_p) : "memory");   \
    if (!_d) {                                                                  \
        asm volatile("{ .reg .pred P1;"                                         \
            " WL_%=:"                                                           \
            " mbarrier.try_wait.parity.acquire.cta.shared::cta.b64 P1, [%0], %1, 0x989680;" \
            " @P1 bra.uni WD_%=;"                                               \
            " bra.uni WL_%=;"                                                   \
            " WD_%=: }" :: "r"(_m), "r"(_p) : "memory");                        \
    }                                                                           \
} while (0)

// SW128 K-major descriptor: layout=SW128(2), version=1, SBO=64, LBO=1
__device__ __forceinline__ uint64_t make_desc(uint32_t addr) {
    const uint64_t base = (uint64_t(2) << 61) | (uint64_t(1) << 46) |
                          (uint64_t(64) << 32) | (uint64_t(1) << 16);
    return base | ((uint64_t)(addr >> 4) & 0x3FFF);
}
// idesc: F32 accum (1<<4), fp16 A/B (0), N=128 (16<<17), M=128 (8<<24)
#define TC_IDESC ((1u << 4) | (16u << 17) | (8u << 24))

__device__ __forceinline__ void mma_f16_ss(uint32_t d, uint64_t a, uint64_t b, uint32_t en) {
    asm volatile(
        "{ .reg .pred p; setp.ne.u32 p, %5, 0;"
        " tcgen05.mma.cta_group::1.kind::f16 [%0], %1, %2, %3, {%4,%4,%4,%4}, p; }"
        :: "r"(d), "l"(a), "l"(b), "r"(TC_IDESC), "r"(0u), "r"(en) : "memory");
}
#define TC_COMMIT(mb) asm volatile( \
    "tcgen05.commit.cta_group::1.mbarrier::arrive::one.shared::cluster.b64 [%0];" \
    :: "r"(mb) : "memory")
#define TC_LD_X32(r, a) asm volatile( \
    "tcgen05.ld.sync.aligned.32x32b.x32.b32 " \
    "{%0,%1,%2,%3,%4,%5,%6,%7,%8,%9,%10,%11,%12,%13,%14,%15," \
    "%16,%17,%18,%19,%20,%21,%22,%23,%24,%25,%26,%27,%28,%29,%30,%31}, [%32];" \
    : "=r"((r)[0]),"=r"((r)[1]),"=r"((r)[2]),"=r"((r)[3]),"=r"((r)[4]),"=r"((r)[5]),"=r"((r)[6]),"=r"((r)[7]), \
      "=r"((r)[8]),"=r"((r)[9]),"=r"((r)[10]),"=r"((r)[11]),"=r"((r)[12]),"=r"((r)[13]),"=r"((r)[14]),"=r"((r)[15]), \
      "=r"((r)[16]),"=r"((r)[17]),"=r"((r)[18]),"=r"((r)[19]),"=r"((r)[20]),"=r"((r)[21]),"=r"((r)[22]),"=r"((r)[23]), \
      "=r"((r)[24]),"=r"((r)[25]),"=r"((r)[26]),"=r"((r)[27]),"=r"((r)[28]),"=r"((r)[29]),"=r"((r)[30]),"=r"((r)[31]) \
    : "r"(a))
#endif  // TC_PATH

// =============================================================================
// unified GEMM, 128 threads, tile 128x128:
//   sm_103a cubin : tcgen05 SS-mode MMA, TMEM f32 accumulator, 2-stage pipeline
//   other cubins  : HMMA warp 64x64, 3-stage cp.async + reg fragment pipelining
// C[m,n] = alpha * sum_k A[m,k]*B[n,k] (+ bias[n] for EPI 0/1)
// EPI 0: fp16 out [(m0+r)*ldc + n0+c] + bias          [Q/K proj]
// EPI 1: fp16 out [(n0+r)*ldc + m0+c] + bias (transp) [V proj]
// EPI 2: f32  out [(m0+r)*ldc + n0+c] * alpha          [scores / weighted]
// =============================================================================
#define SMEM_G 68096   // 1024 align slack + max(1024 + 66048 sf, 2*32768 stages)

template <int EPI>
__global__ void __launch_bounds__(128, 2)
gemm128(const __half* __restrict__ A, const __half* __restrict__ B,
        const float* __restrict__ bias,
        float* __restrict__ Cf, __half* __restrict__ Ch,
        int K, int lda, int ldb, int ldc,
        long sA, long sB, long sC, float alpha)
{
    extern __shared__ char smem_raw[];
    const uint32_t raw32 = smem_u32(smem_raw);
    const uint32_t sbase = (raw32 + 1023) & ~1023u;
    char* smem_al = smem_raw + (sbase - raw32);

    const int tid = threadIdx.x;
    const int w = tid >> 5, l = tid & 31;
    const int m0 = blockIdx.y * 128;
    const int n0 = blockIdx.x * 128;
    const int z = blockIdx.z;

    const __half* Ab = A + z * sA;
    const __half* Bb = B + z * sB;

    float* sf;   // epilogue staging [128][129], set per path

#if TC_PATH
    // ---------------- tcgen05 path ----------------
    const uint32_t TM_PTR = sbase;
    const uint32_t MB = sbase + 8;                 // two mbars: +8, +16
    const uint32_t TILES = sbase + 1024;           // stage s: +s*32768 (A +0, B +16384)

    if (w == 0) {
        asm volatile("tcgen05.alloc.cta_group::1.sync.aligned.shared::cta.b32 [%0], %1;"
                     :: "r"(TM_PTR), "r"(128u) : "memory");
        asm volatile("tcgen05.relinquish_alloc_permit.cta_group::1.sync.aligned;");
    }
    if (tid == 0) { MBAR_INIT(MB, 1); MBAR_INIT(MB + 8, 1); }
    __syncthreads();
    uint32_t tmem;
    asm volatile("ld.shared.b32 %0, [%1];" : "=r"(tmem) : "r"(TM_PTR));

    auto load_stage = [&](int c) {
        const uint32_t stg = TILES + (c & 1) * 32768;
        #pragma unroll
        for (int i = 0; i < 16; i++) {
            int id = tid + i * 128;                // 0..2047
            int t = id >> 10;                      // 0:A 1:B
            int rem = id & 1023;
            int row = rem >> 3, ch = rem & 7;      // 128 rows x 8 x 16B
            const __half* g = (t == 0)
                ? Ab + (long)(m0 + row) * lda + (long)c * 64 + ch * 8
                : Bb + (long)(n0 + row) * ldb + (long)c * 64 + ch * 8;
            uint32_t o = row * 128 + ch * 16;
            uint32_t sa = stg + t * 16384 + (o ^ ((o >> 3) & 0x70));
            cp16(sa, g);
        }
        asm volatile("cp.async.commit_group;" ::: "memory");
    };

    const int NC = K / 64;
    int pha[2] = {0, 0};

    load_stage(0);
    for (int c = 0; c < NC; c++) {
        if (c + 1 < NC) {
            int s2 = (c + 1) & 1;
            if (c + 1 >= 2) { MBAR_WAIT(MB + s2 * 8, pha[s2]); pha[s2] ^= 1; }
            load_stage(c + 1);
            asm volatile("cp.async.wait_group 1;" ::: "memory");
        } else {
            asm volatile("cp.async.wait_group 0;" ::: "memory");
        }
        __syncthreads();
        if (w == 0) {
            asm volatile("fence.proxy.async.shared::cta;" ::: "memory");
            if (elect_one()) {
                const uint32_t stg = TILES + (c & 1) * 32768;
                uint64_t dA = make_desc(stg), dB = make_desc(stg + 16384);
                #pragma unroll
                for (int ks = 0; ks < 4; ks++)
                    mma_f16_ss(tmem, dA + ks * 2, dB + ks * 2, (c != 0) || (ks != 0));
                TC_COMMIT(MB + (c & 1) * 8);
            }
        }
    }
    { int s = (NC - 2) & 1; MBAR_WAIT(MB + s * 8, pha[s]); pha[s] ^= 1;
      s = (NC - 1) & 1;     MBAR_WAIT(MB + s * 8, pha[s]); pha[s] ^= 1; }
    asm volatile("tcgen05.fence::after_thread_sync;" ::: "memory");
    __syncthreads();

    // TMEM -> sf (stages are dead; reuse their SMEM)
    sf = reinterpret_cast<float*>(smem_al + 1024);
    {
        const int mrow = w * 32 + l;
        #pragma unroll
        for (int c0 = 0; c0 < 128; c0 += 32) {
            uint32_t r[32];
            TC_LD_X32(r, tmem + c0);
            asm volatile("tcgen05.wait::ld.sync.aligned;" ::: "memory");
            #pragma unroll
            for (int j = 0; j < 32; j++) {
                float v = __uint_as_float(r[j]) * alpha;
                if (EPI != 2) v += bias[n0 + c0 + j];
                if (EPI == 1) sf[(c0 + j) * 129 + mrow] = v;
                else          sf[mrow * 129 + c0 + j] = v;
            }
        }
    }
    __syncthreads();
    if (tid == 0) { MBAR_INVAL(MB); MBAR_INVAL(MB + 8); }
    if (w == 0)
        asm volatile("tcgen05.dealloc.cta_group::1.sync.aligned.b32 %0, %1;"
                     :: "r"(tmem), "r"(128u));

#else
    // ---------------- HMMA fallback (R10 body) ----------------
    const int NC = K / 32;

    auto load_stage = [&](int c) {
        const uint32_t stg = sbase + (c % 3) * 16384;
        #pragma unroll
        for (int i = 0; i < 8; i++) {
            int id = tid + i * 128;
            int t = id >> 9, rem = id & 511, row = rem >> 2, ch = rem & 3;
            const __half* g = (t == 0)
                ? Ab + (long)(m0 + row) * lda + (long)c * 32 + ch * 8
                : Bb + (long)(n0 + row) * ldb + (long)c * 32 + ch * 8;
            uint32_t sa = stg + t * 8192 + row * 64 + ((ch ^ ((row >> 1) & 3)) << 4);
            cp16(sa, g);
        }
        asm volatile("cp.async.commit_group;" ::: "memory");
    };

    float acc[4][8][4] = {};
    const int wm = (w & 1) * 64;
    const int wn = (w >> 1) * 64;
    const int matI = l >> 3, rim = l & 7;

    uint32_t fB[2][4][4];
    uint32_t fA[2][4];

    auto ldB = [&](int buf, uint32_t bbase, int kk) {
        #pragma unroll
        for (int p = 0; p < 4; p++) {
            int n = wn + p * 16 + (matI >> 1) * 8 + rim;
            int ch = kk * 2 + (matI & 1);
            ldsm_x4(fB[buf][p], bbase + n * 64 + ((ch ^ ((n >> 1) & 3)) << 4));
        }
    };
    auto ldA = [&](int buf, uint32_t stg, int kk, int mi) {
        int row = wm + mi * 16 + rim + (matI & 1) * 8;
        int ch = kk * 2 + (matI >> 1);
        ldsm_x4(fA[buf], stg + row * 64 + ((ch ^ ((row >> 1) & 3)) << 4));
    };

    load_stage(0);
    load_stage(1);

    for (int c = 0; c < NC; c++) {
        asm volatile("cp.async.wait_group 1;" ::: "memory");
        __syncthreads();
        if (c + 2 < NC) load_stage(c + 2);
        else asm volatile("cp.async.commit_group;" ::: "memory");

        const uint32_t stg = sbase + (c % 3) * 16384;
        const uint32_t bbase = stg + 8192;

        ldB(0, bbase, 0);
        ldA(0, stg, 0, 0);

        #pragma unroll
        for (int kk = 0; kk < 2; kk++) {
            #pragma unroll
            for (int mi = 0; mi < 4; mi++) {
                const int cur = mi & 1;
                if (mi < 3) {
                    ldA(cur ^ 1, stg, kk, mi + 1);
                } else if (kk == 0) {
                    ldB(1, bbase, 1);
                    ldA(cur ^ 1, stg, 1, 0);
                }
                #pragma unroll
                for (int ni = 0; ni < 8; ni++)
                    hmma(acc[mi][ni], fA[cur], &fB[kk][ni >> 1][(ni & 1) * 2]);
            }
        }
    }
    asm volatile("cp.async.wait_group 0;" ::: "memory");
    __syncthreads();

    sf = reinterpret_cast<float*>(smem_al);
    {
        const int r_ = l >> 2, cq = (l & 3) * 2;
        #pragma unroll
        for (int mi = 0; mi < 4; mi++)
            #pragma unroll
            for (int ni = 0; ni < 8; ni++) {
                int m = wm + mi * 16 + r_;
                int n = wn + ni * 8 + cq;
                float b0 = 0.f, b1 = 0.f;
                if (EPI != 2) { b0 = bias[n0 + n]; b1 = bias[n0 + n + 1]; }
                float v00 = acc[mi][ni][0] * alpha + b0;
                float v01 = acc[mi][ni][1] * alpha + b1;
                float v10 = acc[mi][ni][2] * alpha + b0;
                float v11 = acc[mi][ni][3] * alpha + b1;
                if (EPI == 1) {
                    sf[n * 129 + m] = v00;       sf[(n + 1) * 129 + m] = v01;
                    sf[n * 129 + m + 8] = v10;   sf[(n + 1) * 129 + m + 8] = v11;
                } else {
                    sf[m * 129 + n] = v00;       sf[m * 129 + n + 1] = v01;
                    sf[(m + 8) * 129 + n] = v10; sf[(m + 8) * 129 + n + 1] = v11;
                }
            }
    }
    __syncthreads();
#endif

    // ---------------- common GMEM writes ----------------
    if (EPI == 2) {
        float* Cb = Cf + z * sC;
        #pragma unroll
        for (int i = 0; i < 32; i++) {
            int idx = (tid + i * 128) << 2;
            int row = idx >> 7, col = idx & 127;
            const float* p = &sf[row * 129 + col];
            float4 v = make_float4(p[0], p[1], p[2], p[3]);
            *reinterpret_cast<float4*>(Cb + (long)(m0 + row) * ldc + n0 + col) = v;
        }
    } else {
        #pragma unroll
        for (int i = 0; i < 32; i++) {
            int idx = (tid + i * 128) << 2;
            int row = idx >> 7, col = idx & 127;
            const float* p = &sf[row * 129 + col];
            uint32_t hp[2];
            #pragma unroll
            for (int q = 0; q < 2; q++) {
                __half2 H = __halves2half2(__float2half_rn(p[2 * q]),
                                           __float2half_rn(p[2 * q + 1]));
                hp[q] = *reinterpret_cast<uint32_t*>(&H);
            }
            long dst = (EPI == 0) ? ((long)(m0 + row) * ldc + n0 + col)
                                  : ((long)(n0 + row) * ldc + m0 + col);
            *reinterpret_cast<uint2*>(Ch + dst) = make_uint2(hp[0], hp[1]);
        }
    }
}

// ======================= single fused conversion: x + Wq + Wk + Wv -> fp16 =======================
__global__ void cvt_all(const float* __restrict__ x,
                        const float* __restrict__ Wq, const float* __restrict__ Wk,
                        const float* __restrict__ Wv,
                        __half* __restrict__ Xh, __half* __restrict__ Wh,
                        int NX4, int NW4)
{
    int i = blockIdx.x * blockDim.x + threadIdx.x;
    if (i < NX4) {
        float4 v = reinterpret_cast<const float4*>(x)[i];
        __half2 h0 = __floats2half2_rn(v.x, v.y), h1 = __floats2half2_rn(v.z, v.w);
        reinterpret_cast<uint2*>(Xh)[i] = make_uint2(*(uint32_t*)&h0, *(uint32_t*)&h1);
    } else {
        int k = i - NX4;
        if (k >= 3 * NW4) return;
        int s = k / NW4;
        int j = k - s * NW4;
        const float* src = (s == 0) ? Wq : (s == 1) ? Wk : Wv;
        float4 v = reinterpret_cast<const float4*>(src)[j];
        __half2 h0 = __floats2half2_rn(v.x, v.y), h1 = __floats2half2_rn(v.z, v.w);
        reinterpret_cast<uint2*>(Wh)[k] = make_uint2(*(uint32_t*)&h0, *(uint32_t*)&h1);
    }
}

// ======================= softmax (f32 in place + fp16 out), float4 =======================
__global__ void __launch_bounds__(256) softmax_kernel(
    float* __restrict__ att, __half* __restrict__ Ph)
{
    const int S = 2048;
    const long rowoff = (long)blockIdx.x * S;
    float4* row4 = reinterpret_cast<float4*>(att + rowoff);
    const int t = threadIdx.x, lane = t & 31, warp = t >> 5;

    __shared__ float red_max[8], red_sum[8];

    float4 v[2];
    float vmax = -1e30f;
    #pragma unroll
    for (int i = 0; i < 2; i++) {
        v[i] = row4[t + i * 256];
        vmax = fmaxf(vmax, fmaxf(fmaxf(v[i].x, v[i].y), fmaxf(v[i].z, v[i].w)));
    }
    #pragma unroll
    for (int o = 16; o > 0; o >>= 1) vmax = fmaxf(vmax, __shfl_xor_sync(~0u, vmax, o));
    if (lane == 0) red_max[warp] = vmax;
    __syncthreads();
    vmax = red_max[0];
    #pragma unroll
    for (int i = 1; i < 8; i++) vmax = fmaxf(vmax, red_max[i]);

    float sum = 0.f;
    #pragma unroll
    for (int i = 0; i < 2; i++) {
        v[i].x = __expf(v[i].x - vmax); v[i].y = __expf(v[i].y - vmax);
        v[i].z = __expf(v[i].z - vmax); v[i].w = __expf(v[i].w - vmax);
        sum += (v[i].x + v[i].y) + (v[i].z + v[i].w);
    }
    #pragma unroll
    for (int o = 16; o > 0; o >>= 1) sum += __shfl_xor_sync(~0u, sum, o);
    if (lane == 0) red_sum[warp] = sum;
    __syncthreads();
    float tot = red_sum[0];
    #pragma unroll
    for (int i = 1; i < 8; i++) tot += red_sum[i];
    float inv = 1.0f / tot;

    uint2* Ph2 = reinterpret_cast<uint2*>(Ph + rowoff);
    #pragma unroll
    for (int i = 0; i < 2; i++) {
        float4 p;
        p.x = v[i].x * inv; p.y = v[i].y * inv;
        p.z = v[i].z * inv; p.w = v[i].w * inv;
        row4[t + i * 256] = p;
        __half2 a = __floats2half2_rn(p.x, p.y), b = __floats2half2_rn(p.z, p.w);
        Ph2[t + i * 256] = make_uint2(*(uint32_t*)&a, *(uint32_t*)&b);
    }
}

// ======================= launch =======================
extern "C" void kernel_launch(void* const* d_in, const int* in_sizes, int n_in,
                              void* d_out, int out_size)
{
    const float* x  = (const float*)d_in[0];
    const float* Wq = (const float*)d_in[1];
    const float* bq = (const float*)d_in[2];
    const float* Wk = (const float*)d_in[3];
    const float* bk = (const float*)d_in[4];
    const float* Wv = (const float*)d_in[5];
    const float* bv = (const float*)d_in[6];

    const int B = 4, S = 2048, D = 512;
    float* att = (float*)d_out;
    float* wtd = att + (size_t)B * S * S;

    __half *Xh, *Wh, *Qh, *Kh, *Vth, *Ph;
    cudaGetSymbolAddress((void**)&Xh, g_Xh);
    cudaGetSymbolAddress((void**)&Wh, g_Wh);
    cudaGetSymbolAddress((void**)&Qh, g_Qh);
    cudaGetSymbolAddress((void**)&Kh, g_Kh);
    cudaGetSymbolAddress((void**)&Vth, g_Vth);
    cudaGetSymbolAddress((void**)&Ph, g_Ph);

    cudaFuncSetAttribute(gemm128<0>, cudaFuncAttributeMaxDynamicSharedMemorySize, SMEM_G);
    cudaFuncSetAttribute(gemm128<1>, cudaFuncAttributeMaxDynamicSharedMemorySize, SMEM_G);
    cudaFuncSetAttribute(gemm128<2>, cudaFuncAttributeMaxDynamicSharedMemorySize, SMEM_G);

    const int NX4 = B * S * D / 4;       // 1048576
    const int NW4 = D * D / 4;           // 65536
    const int NALL = NX4 + 3 * NW4;
    cvt_all<<<(NALL + 255) / 256, 256>>>(x, Wq, Wk, Wv, Xh, Wh, NX4, NW4);

    // projections (1-term fp16): Q, K normal; V transposed into Vth [512, 8192]
    dim3 gproj(D / 128, (B * S) / 128, 1);
    gemm128<0><<<gproj, 128, SMEM_G>>>(Xh, Wh, bq, nullptr, Qh,
                                       D, D, D, D, 0, 0, 0, 1.0f);
    gemm128<0><<<gproj, 128, SMEM_G>>>(Xh, Wh + D * D, bk, nullptr, Kh,
                                       D, D, D, D, 0, 0, 0, 1.0f);
    gemm128<1><<<gproj, 128, SMEM_G>>>(Xh, Wh + 2 * D * D, bv, nullptr, Vth,
                                       D, D, D, 8192, 0, 0, 0, 1.0f);

    // scores: att[b] = Q[b] @ K[b]^T * scale
    const float scale = 1.0f / sqrtf((float)D);
    dim3 gsc(S / 128, S / 128, B);
    gemm128<2><<<gsc, 128, SMEM_G>>>(Qh, Kh, nullptr, att, nullptr,
                                     D, D, D, S,
                                     (long)S * D, (long)S * D, (long)S * S, scale);

    // softmax
    softmax_kernel<<<B * S, 256>>>(att, Ph);

    // weighted: wtd[b] = P[b] @ V[b]  (Vt is [512, 8192], per-batch col offset b*2048)
    dim3 gw(D / 128, S / 128, B);
    gemm128<2><<<gw, 128, SMEM_G>>>(Ph, Vth, nullptr, wtd, nullptr,
                                    S, S, 8192, D,
                                    (long)S * S, (long)S, (long)S * D, 1.0f);
}